// round 1
// baseline (speedup 1.0000x reference)
#include <cuda_runtime.h>
#include <cstdint>
#include <cstddef>

#define NN 100000
#define IN_DIM 128
#define HID_DIM 128
#define LAT_DIM 64

// Scratch (no cudaMalloc allowed): 128 MB of __device__ globals.
__device__ float g_t1[(size_t)NN * HID_DIM];    // x @ W1
__device__ float g_agg1[(size_t)NN * HID_DIM];  // A @ t1
__device__ float g_t2[(size_t)NN * LAT_DIM];    // relu(agg1+b1) @ W2

// ---------------------------------------------------------------------------
// init: agg1 = 0 ; out[n][c] = b2[c]
// ---------------------------------------------------------------------------
__global__ void __launch_bounds__(256) init_kernel(float* __restrict__ agg1,
                                                   float* __restrict__ out,
                                                   const float* __restrict__ b2) {
    const int idx = blockIdx.x * blockDim.x + threadIdx.x;
    const int stride = gridDim.x * blockDim.x;
    const int n1 = NN * HID_DIM / 4;
    for (int i = idx; i < n1; i += stride)
        ((float4*)agg1)[i] = make_float4(0.f, 0.f, 0.f, 0.f);
    const int n2 = NN * LAT_DIM / 4;
    for (int i = idx; i < n2; i += stride) {
        const float4 bv = *(const float4*)(b2 + (i & 15) * 4);
        ((float4*)out)[i] = bv;
    }
}

// ---------------------------------------------------------------------------
// gemm_l1: t1[M,128] = X[M,128] @ W[128,128]
// block tile 64 rows x 128 cols, 256 threads, per-thread 4x8 register tile
// ---------------------------------------------------------------------------
__global__ void __launch_bounds__(256) gemm_l1(const float* __restrict__ X,
                                               const float* __restrict__ W,
                                               float* __restrict__ out) {
    extern __shared__ float sm[];
    float* xs = sm;               // [64][132] (padded rows)
    float* ws = sm + 64 * 132;    // [128][128]
    const int tid = threadIdx.x;
    const int row0 = blockIdx.x * 64;

    for (int i = tid; i < 128 * 128 / 4; i += 256)
        ((float4*)ws)[i] = ((const float4*)W)[i];

    for (int i = tid; i < 64 * 32; i += 256) {
        const int r = i >> 5, c4 = i & 31;
        float4 v = make_float4(0.f, 0.f, 0.f, 0.f);
        if (row0 + r < NN)
            v = *(const float4*)(X + (size_t)(row0 + r) * 128 + c4 * 4);
        *(float4*)(xs + r * 132 + c4 * 4) = v;
    }
    __syncthreads();

    const int tc = (tid & 15) * 8;   // 16 col groups * 8 cols
    const int tr = (tid >> 4) * 4;   // 16 row groups * 4 rows
    float acc[4][8];
#pragma unroll
    for (int i = 0; i < 4; i++)
#pragma unroll
        for (int j = 0; j < 8; j++) acc[i][j] = 0.f;

#pragma unroll 8
    for (int k = 0; k < 128; k++) {
        float a[4];
#pragma unroll
        for (int i = 0; i < 4; i++) a[i] = xs[(tr + i) * 132 + k];
        const float4 b0 = *(const float4*)(ws + k * 128 + tc);
        const float4 b1 = *(const float4*)(ws + k * 128 + tc + 4);
#pragma unroll
        for (int i = 0; i < 4; i++) {
            acc[i][0] += a[i] * b0.x; acc[i][1] += a[i] * b0.y;
            acc[i][2] += a[i] * b0.z; acc[i][3] += a[i] * b0.w;
            acc[i][4] += a[i] * b1.x; acc[i][5] += a[i] * b1.y;
            acc[i][6] += a[i] * b1.z; acc[i][7] += a[i] * b1.w;
        }
    }

#pragma unroll
    for (int i = 0; i < 4; i++) {
        const int r = row0 + tr + i;
        if (r < NN) {
            float4 v0 = make_float4(acc[i][0], acc[i][1], acc[i][2], acc[i][3]);
            float4 v1 = make_float4(acc[i][4], acc[i][5], acc[i][6], acc[i][7]);
            *(float4*)(out + (size_t)r * 128 + tc) = v0;
            *(float4*)(out + (size_t)r * 128 + tc + 4) = v1;
        }
    }
}

// ---------------------------------------------------------------------------
// gemm_l2: t2[M,64] = relu(AGG[M,128] + b1) @ W[128,64]
// bias + relu fused into the smem tile load.
// ---------------------------------------------------------------------------
__global__ void __launch_bounds__(256) gemm_l2(const float* __restrict__ AGG,
                                               const float* __restrict__ B1,
                                               const float* __restrict__ W,
                                               float* __restrict__ out) {
    extern __shared__ float sm[];
    float* xs = sm;               // [64][132]
    float* ws = sm + 64 * 132;    // [128][64]
    const int tid = threadIdx.x;
    const int row0 = blockIdx.x * 64;

    for (int i = tid; i < 128 * 64 / 4; i += 256)
        ((float4*)ws)[i] = ((const float4*)W)[i];

    for (int i = tid; i < 64 * 32; i += 256) {
        const int r = i >> 5, c4 = i & 31;
        float4 v = make_float4(0.f, 0.f, 0.f, 0.f);
        if (row0 + r < NN) {
            v = *(const float4*)(AGG + (size_t)(row0 + r) * 128 + c4 * 4);
            const float4 bv = *(const float4*)(B1 + c4 * 4);
            v.x = fmaxf(v.x + bv.x, 0.f);
            v.y = fmaxf(v.y + bv.y, 0.f);
            v.z = fmaxf(v.z + bv.z, 0.f);
            v.w = fmaxf(v.w + bv.w, 0.f);
        }
        *(float4*)(xs + r * 132 + c4 * 4) = v;
    }
    __syncthreads();

    const int tc = (tid & 15) * 4;   // 16 col groups * 4 cols = 64
    const int tr = (tid >> 4) * 4;
    float acc[4][4];
#pragma unroll
    for (int i = 0; i < 4; i++)
#pragma unroll
        for (int j = 0; j < 4; j++) acc[i][j] = 0.f;

#pragma unroll 8
    for (int k = 0; k < 128; k++) {
        float a[4];
#pragma unroll
        for (int i = 0; i < 4; i++) a[i] = xs[(tr + i) * 132 + k];
        const float4 b0 = *(const float4*)(ws + k * 64 + tc);
#pragma unroll
        for (int i = 0; i < 4; i++) {
            acc[i][0] += a[i] * b0.x; acc[i][1] += a[i] * b0.y;
            acc[i][2] += a[i] * b0.z; acc[i][3] += a[i] * b0.w;
        }
    }

#pragma unroll
    for (int i = 0; i < 4; i++) {
        const int r = row0 + tr + i;
        if (r < NN) {
            float4 v0 = make_float4(acc[i][0], acc[i][1], acc[i][2], acc[i][3]);
            *(float4*)(out + (size_t)r * 64 + tc) = v0;
        }
    }
}

// ---------------------------------------------------------------------------
// spmm: Y[dst] += val * X[src], feature dim D (128 or 64).
// Warp loads 32 edges coalesced, shfl-broadcasts each, lane-parallel float4
// gather + vectorized red.global.add.v4.f32 scatter.
// ---------------------------------------------------------------------------
template <int D>
__global__ void __launch_bounds__(256) spmm_kernel(const int* __restrict__ src,
                                                   const int* __restrict__ dst,
                                                   const float* __restrict__ vals,
                                                   const float* __restrict__ X,
                                                   float* __restrict__ Y, int E) {
    constexpr int LPE = D / 4;      // lanes per edge (32 for D=128, 16 for D=64)
    constexpr int EPS = 32 / LPE;   // edges per step
    const int lane = threadIdx.x & 31;
    const int gwarp = (blockIdx.x * blockDim.x + threadIdx.x) >> 5;
    const int nwarp = (gridDim.x * blockDim.x) >> 5;
    const int sub = lane / LPE;
    const int off = (lane % LPE) * 4;

    for (int base = gwarp * 32; base < E; base += nwarp * 32) {
        const int e = base + lane;
        int s = 0, d = 0;
        float v = 0.f;
        if (e < E) { s = src[e]; d = dst[e]; v = vals[e]; }
        const int cnt = min(32, E - base);
#pragma unroll 4
        for (int step = 0; step < 32 / EPS; step++) {
            const int j = step * EPS + sub;
            const int sj = __shfl_sync(0xffffffffu, s, j);
            const int dj = __shfl_sync(0xffffffffu, d, j);
            const float vj = __shfl_sync(0xffffffffu, v, j);
            if (j < cnt) {
                const float4 xv = __ldg((const float4*)(X + (size_t)sj * D + off));
                float* p = Y + (size_t)dj * D + off;
                asm volatile(
                    "red.global.add.v4.f32 [%0], {%1, %2, %3, %4};" ::"l"(p),
                    "f"(xv.x * vj), "f"(xv.y * vj), "f"(xv.z * vj), "f"(xv.w * vj)
                    : "memory");
            }
        }
    }
}

// ---------------------------------------------------------------------------
extern "C" void kernel_launch(void* const* d_in, const int* in_sizes, int n_in,
                              void* d_out, int out_size) {
    const float* x  = (const float*)d_in[0];
    const int*   es = (const int*)d_in[1];
    const int*   ed = (const int*)d_in[2];
    const float* ev = (const float*)d_in[3];
    const float* W1 = (const float*)d_in[4];
    const float* b1 = (const float*)d_in[5];
    const float* W2 = (const float*)d_in[6];
    const float* b2 = (const float*)d_in[7];
    float* out = (float*)d_out;
    const int E = in_sizes[1];

    float *t1, *agg1, *t2;
    cudaGetSymbolAddress((void**)&t1, g_t1);
    cudaGetSymbolAddress((void**)&agg1, g_agg1);
    cudaGetSymbolAddress((void**)&t2, g_t2);

    const int SM1 = (64 * 132 + 128 * 128) * 4;  // ~97 KB
    const int SM2 = (64 * 132 + 128 * 64) * 4;   // ~65 KB
    cudaFuncSetAttribute(gemm_l1, cudaFuncAttributeMaxDynamicSharedMemorySize, SM1);
    cudaFuncSetAttribute(gemm_l2, cudaFuncAttributeMaxDynamicSharedMemorySize, SM2);

    const int gemm_blocks = (NN + 63) / 64;
    const int spmm_blocks = (E + 32 * 8 - 1) / (32 * 8);  // 8 warps/block, 32 edges/warp

    init_kernel<<<2048, 256>>>(agg1, out, b2);
    gemm_l1<<<gemm_blocks, 256, SM1>>>(x, W1, t1);
    spmm_kernel<128><<<spmm_blocks, 256>>>(es, ed, ev, t1, agg1, E);
    gemm_l2<<<gemm_blocks, 256, SM2>>>(agg1, b1, W2, t2);
    spmm_kernel<64><<<spmm_blocks, 256>>>(es, ed, ev, t2, out, E);
}

// round 2
// speedup vs baseline: 1.0187x; 1.0187x over previous
#include <cuda_runtime.h>
#include <cstdint>
#include <cstddef>

#define NN 100000
#define NE 1600000
#define IN_DIM 128
#define HID_DIM 128
#define LAT_DIM 64

// Scratch (no cudaMalloc allowed): __device__ globals.
__device__ float g_t1[(size_t)NN * HID_DIM];    // x @ W1
__device__ float g_agg1[(size_t)NN * HID_DIM];  // A @ t1
__device__ float g_t2[(size_t)NN * LAT_DIM];    // relu(agg1+b1) @ W2
__device__ int   g_deg[NN];                     // in-degree histogram
__device__ int   g_off[NN + 1];                 // CSR row offsets (by dst)
__device__ int   g_cur[NN];                     // scatter cursors
__device__ int2  g_edge[NE];                    // dst-sorted (src, val_bits)

// ---------------------------------------------------------------------------
// Sort pipeline: zero -> histogram -> scan -> scatter
// ---------------------------------------------------------------------------
__global__ void __launch_bounds__(256) zero_deg() {
    const int i = blockIdx.x * blockDim.x + threadIdx.x;
    if (i < NN) g_deg[i] = 0;
}

__global__ void __launch_bounds__(256) hist_kernel(const int* __restrict__ dst, int E) {
    const int i = blockIdx.x * blockDim.x + threadIdx.x;
    if (i < E) atomicAdd(&g_deg[dst[i]], 1);
}

// single-block two-level exclusive scan over NN degrees
__global__ void __launch_bounds__(1024) scan_kernel(int E) {
    __shared__ int ssum[1024];
    const int t = threadIdx.x;
    const int CH = (NN + 1023) / 1024;  // 98
    const int lo = t * CH;
    const int hi = min(lo + CH, NN);
    int s = 0;
    for (int i = lo; i < hi; i++) s += g_deg[i];
    const int mysum = s;
    ssum[t] = s;
    __syncthreads();
    // inclusive Hillis-Steele scan
    for (int d = 1; d < 1024; d <<= 1) {
        int add = (t >= d) ? ssum[t - d] : 0;
        __syncthreads();
        ssum[t] += add;
        __syncthreads();
    }
    int run = ssum[t] - mysum;  // exclusive prefix
    for (int i = lo; i < hi; i++) {
        g_off[i] = run;
        g_cur[i] = run;
        run += g_deg[i];
    }
    if (t == 1023) g_off[NN] = run;  // == E
}

__global__ void __launch_bounds__(256) scatter_kernel(const int* __restrict__ src,
                                                      const int* __restrict__ dst,
                                                      const float* __restrict__ vals,
                                                      int E) {
    const int i = blockIdx.x * blockDim.x + threadIdx.x;
    if (i < E) {
        const int d = dst[i];
        const int p = atomicAdd(&g_cur[d], 1);
        g_edge[p] = make_int2(src[i], __float_as_int(vals[i]));
    }
}

// ---------------------------------------------------------------------------
// gemm_l1: t1[M,128] = X[M,128] @ W[128,128]
// BM=128, BK=32, 256 threads, 8x8 per-thread tile, A stored k-major in smem.
// ---------------------------------------------------------------------------
__global__ void __launch_bounds__(256) gemm_l1(const float* __restrict__ X,
                                               const float* __restrict__ W,
                                               float* __restrict__ out) {
    extern __shared__ float sm[];
    float* ws = sm;                 // [128][128]  (k-major: ws[k*128+n])
    float* xs = sm + 128 * 128;     // [32][132]   (xs[k*132+row])
    const int tid = threadIdx.x;
    const int tx = tid & 15;        // 16 col groups * 8
    const int ty = tid >> 4;        // 16 row groups * 8
    const int row0 = blockIdx.x * 128;

    for (int i = tid; i < 128 * 128 / 4; i += 256)
        ((float4*)ws)[i] = ((const float4*)W)[i];

    float acc[8][8];
#pragma unroll
    for (int i = 0; i < 8; i++)
#pragma unroll
        for (int j = 0; j < 8; j++) acc[i][j] = 0.f;

    for (int kc = 0; kc < 128; kc += 32) {
        __syncthreads();
#pragma unroll
        for (int j = 0; j < 4; j++) {
            const int f = tid + j * 256;   // 1024 float4s in the 128x32 chunk
            const int r = f >> 3;
            const int c4 = f & 7;
            float4 v = make_float4(0.f, 0.f, 0.f, 0.f);
            if (row0 + r < NN)
                v = *(const float4*)(X + (size_t)(row0 + r) * 128 + kc + c4 * 4);
            xs[(c4 * 4 + 0) * 132 + r] = v.x;
            xs[(c4 * 4 + 1) * 132 + r] = v.y;
            xs[(c4 * 4 + 2) * 132 + r] = v.z;
            xs[(c4 * 4 + 3) * 132 + r] = v.w;
        }
        __syncthreads();

#pragma unroll 8
        for (int k = 0; k < 32; k++) {
            float a[8], b[8];
            *(float4*)(a)     = *(const float4*)(xs + k * 132 + ty * 8);
            *(float4*)(a + 4) = *(const float4*)(xs + k * 132 + ty * 8 + 4);
            *(float4*)(b)     = *(const float4*)(ws + (kc + k) * 128 + tx * 8);
            *(float4*)(b + 4) = *(const float4*)(ws + (kc + k) * 128 + tx * 8 + 4);
#pragma unroll
            for (int i = 0; i < 8; i++)
#pragma unroll
                for (int j = 0; j < 8; j++) acc[i][j] += a[i] * b[j];
        }
    }

#pragma unroll
    for (int i = 0; i < 8; i++) {
        const int r = row0 + ty * 8 + i;
        if (r < NN) {
            *(float4*)(out + (size_t)r * 128 + tx * 8) =
                make_float4(acc[i][0], acc[i][1], acc[i][2], acc[i][3]);
            *(float4*)(out + (size_t)r * 128 + tx * 8 + 4) =
                make_float4(acc[i][4], acc[i][5], acc[i][6], acc[i][7]);
        }
    }
}

// ---------------------------------------------------------------------------
// gemm_l2: t2[M,64] = relu(AGG[M,128] + b1) @ W[128,64]
// BM=128, BN=64, BK=32, 128 threads, 8x8 per-thread tile.
// ---------------------------------------------------------------------------
__global__ void __launch_bounds__(128) gemm_l2(const float* __restrict__ AGG,
                                               const float* __restrict__ B1,
                                               const float* __restrict__ W,
                                               float* __restrict__ out) {
    extern __shared__ float sm[];
    float* ws = sm;                 // [128][64]
    float* xs = sm + 128 * 64;      // [32][132]
    const int tid = threadIdx.x;
    const int tx = tid & 7;         // 8 col groups * 8 = 64
    const int ty = tid >> 3;        // 16 row groups * 8 = 128
    const int row0 = blockIdx.x * 128;

    for (int i = tid; i < 128 * 64 / 4; i += 128)
        ((float4*)ws)[i] = ((const float4*)W)[i];

    float acc[8][8];
#pragma unroll
    for (int i = 0; i < 8; i++)
#pragma unroll
        for (int j = 0; j < 8; j++) acc[i][j] = 0.f;

    for (int kc = 0; kc < 128; kc += 32) {
        __syncthreads();
#pragma unroll
        for (int j = 0; j < 8; j++) {
            const int f = tid + j * 128;
            const int r = f >> 3;
            const int c4 = f & 7;
            float4 v = make_float4(0.f, 0.f, 0.f, 0.f);
            if (row0 + r < NN) {
                v = *(const float4*)(AGG + (size_t)(row0 + r) * 128 + kc + c4 * 4);
                const float4 bv = *(const float4*)(B1 + kc + c4 * 4);
                v.x = fmaxf(v.x + bv.x, 0.f);
                v.y = fmaxf(v.y + bv.y, 0.f);
                v.z = fmaxf(v.z + bv.z, 0.f);
                v.w = fmaxf(v.w + bv.w, 0.f);
            }
            xs[(c4 * 4 + 0) * 132 + r] = v.x;
            xs[(c4 * 4 + 1) * 132 + r] = v.y;
            xs[(c4 * 4 + 2) * 132 + r] = v.z;
            xs[(c4 * 4 + 3) * 132 + r] = v.w;
        }
        __syncthreads();

#pragma unroll 8
        for (int k = 0; k < 32; k++) {
            float a[8], b[8];
            *(float4*)(a)     = *(const float4*)(xs + k * 132 + ty * 8);
            *(float4*)(a + 4) = *(const float4*)(xs + k * 132 + ty * 8 + 4);
            *(float4*)(b)     = *(const float4*)(ws + (kc + k) * 64 + tx * 8);
            *(float4*)(b + 4) = *(const float4*)(ws + (kc + k) * 64 + tx * 8 + 4);
#pragma unroll
            for (int i = 0; i < 8; i++)
#pragma unroll
                for (int j = 0; j < 8; j++) acc[i][j] += a[i] * b[j];
        }
    }

#pragma unroll
    for (int i = 0; i < 8; i++) {
        const int r = row0 + ty * 8 + i;
        if (r < NN) {
            *(float4*)(out + (size_t)r * 64 + tx * 8) =
                make_float4(acc[i][0], acc[i][1], acc[i][2], acc[i][3]);
            *(float4*)(out + (size_t)r * 64 + tx * 8 + 4) =
                make_float4(acc[i][4], acc[i][5], acc[i][6], acc[i][7]);
        }
    }
}

// ---------------------------------------------------------------------------
// spmm_gather<128>: one warp per dst row; lane owns float4 (4 cols).
// Y[row] = sum_e val_e * X[src_e]   (no atomics, single coalesced write)
// ---------------------------------------------------------------------------
__global__ void __launch_bounds__(256) spmm_gather128(const float* __restrict__ X,
                                                      float* __restrict__ Y) {
    const int lane = threadIdx.x & 31;
    const int row = (blockIdx.x * blockDim.x + threadIdx.x) >> 5;
    if (row >= NN) return;
    const int beg = g_off[row];
    const int end = g_off[row + 1];
    const float4* Xv = (const float4*)X;

    float4 acc = make_float4(0.f, 0.f, 0.f, 0.f);
    int e = beg;
    for (; e + 4 <= end; e += 4) {
        const int2 e0 = g_edge[e], e1 = g_edge[e + 1], e2 = g_edge[e + 2], e3 = g_edge[e + 3];
        const float4 x0 = Xv[(size_t)e0.x * 32 + lane];
        const float4 x1 = Xv[(size_t)e1.x * 32 + lane];
        const float4 x2 = Xv[(size_t)e2.x * 32 + lane];
        const float4 x3 = Xv[(size_t)e3.x * 32 + lane];
        const float v0 = __int_as_float(e0.y), v1 = __int_as_float(e1.y);
        const float v2 = __int_as_float(e2.y), v3 = __int_as_float(e3.y);
        acc.x += v0 * x0.x + v1 * x1.x + v2 * x2.x + v3 * x3.x;
        acc.y += v0 * x0.y + v1 * x1.y + v2 * x2.y + v3 * x3.y;
        acc.z += v0 * x0.z + v1 * x1.z + v2 * x2.z + v3 * x3.z;
        acc.w += v0 * x0.w + v1 * x1.w + v2 * x2.w + v3 * x3.w;
    }
    for (; e < end; e++) {
        const int2 ee = g_edge[e];
        const float4 xv = Xv[(size_t)ee.x * 32 + lane];
        const float v = __int_as_float(ee.y);
        acc.x += v * xv.x; acc.y += v * xv.y; acc.z += v * xv.z; acc.w += v * xv.w;
    }
    ((float4*)Y)[(size_t)row * 32 + lane] = acc;
}

// spmm_gather<64>: one warp per dst row; lane owns float2. Fuses +b2 epilogue.
__global__ void __launch_bounds__(256) spmm_gather64(const float* __restrict__ X,
                                                     const float* __restrict__ B2,
                                                     float* __restrict__ Y) {
    const int lane = threadIdx.x & 31;
    const int row = (blockIdx.x * blockDim.x + threadIdx.x) >> 5;
    if (row >= NN) return;
    const int beg = g_off[row];
    const int end = g_off[row + 1];
    const float2* Xv = (const float2*)X;

    float2 acc = make_float2(0.f, 0.f);
    int e = beg;
    for (; e + 4 <= end; e += 4) {
        const int2 e0 = g_edge[e], e1 = g_edge[e + 1], e2 = g_edge[e + 2], e3 = g_edge[e + 3];
        const float2 x0 = Xv[(size_t)e0.x * 32 + lane];
        const float2 x1 = Xv[(size_t)e1.x * 32 + lane];
        const float2 x2 = Xv[(size_t)e2.x * 32 + lane];
        const float2 x3 = Xv[(size_t)e3.x * 32 + lane];
        const float v0 = __int_as_float(e0.y), v1 = __int_as_float(e1.y);
        const float v2 = __int_as_float(e2.y), v3 = __int_as_float(e3.y);
        acc.x += v0 * x0.x + v1 * x1.x + v2 * x2.x + v3 * x3.x;
        acc.y += v0 * x0.y + v1 * x1.y + v2 * x2.y + v3 * x3.y;
    }
    for (; e < end; e++) {
        const int2 ee = g_edge[e];
        const float2 xv = Xv[(size_t)ee.x * 32 + lane];
        const float v = __int_as_float(ee.y);
        acc.x += v * xv.x; acc.y += v * xv.y;
    }
    const float2 bv = *(const float2*)(B2 + lane * 2);
    acc.x += bv.x; acc.y += bv.y;
    ((float2*)Y)[(size_t)row * 32 + lane] = acc;
}

// ---------------------------------------------------------------------------
extern "C" void kernel_launch(void* const* d_in, const int* in_sizes, int n_in,
                              void* d_out, int out_size) {
    const float* x  = (const float*)d_in[0];
    const int*   es = (const int*)d_in[1];
    const int*   ed = (const int*)d_in[2];
    const float* ev = (const float*)d_in[3];
    const float* W1 = (const float*)d_in[4];
    const float* b1 = (const float*)d_in[5];
    const float* W2 = (const float*)d_in[6];
    const float* b2 = (const float*)d_in[7];
    float* out = (float*)d_out;
    const int E = in_sizes[1];

    float *t1, *agg1, *t2;
    cudaGetSymbolAddress((void**)&t1, g_t1);
    cudaGetSymbolAddress((void**)&agg1, g_agg1);
    cudaGetSymbolAddress((void**)&t2, g_t2);

    const int SM1 = (128 * 128 + 32 * 132) * 4;  // ~82.4 KB
    const int SM2 = (128 * 64 + 32 * 132) * 4;   // ~49.7 KB
    static bool attr_set = false;
    cudaFuncSetAttribute(gemm_l1, cudaFuncAttributeMaxDynamicSharedMemorySize, SM1);
    cudaFuncSetAttribute(gemm_l2, cudaFuncAttributeMaxDynamicSharedMemorySize, SM2);
    (void)attr_set;

    const int eb = (E + 255) / 256;
    const int gemm_blocks = (NN + 127) / 128;           // 782
    const int spmm_blocks = (NN * 32 + 255) / 256;      // warp per row, 8 warps/block

    // Build dst-sorted CSR edge list (amortized over both SpMMs)
    zero_deg<<<(NN + 255) / 256, 256>>>();
    hist_kernel<<<eb, 256>>>(ed, E);
    scan_kernel<<<1, 1024>>>(E);
    scatter_kernel<<<eb, 256>>>(es, ed, ev, E);

    // t1 = x @ W1
    gemm_l1<<<gemm_blocks, 256, SM1>>>(x, W1, t1);
    // agg1 = A @ t1
    spmm_gather128<<<spmm_blocks, 256>>>(t1, agg1);
    // t2 = relu(agg1 + b1) @ W2
    gemm_l2<<<gemm_blocks, 128, SM2>>>(agg1, b1, W2, t2);
    // out = A @ t2 + b2
    spmm_gather64<<<spmm_blocks, 256>>>(t2, b2, out);
}

// round 4
// speedup vs baseline: 1.1216x; 1.1010x over previous
#include <cuda_runtime.h>
#include <cuda_bf16.h>
#include <cstdint>
#include <cstddef>

#define NN 100000
#define NE 1600000
#define IN_DIM 128
#define HID_DIM 128
#define LAT_DIM 64

// ---------------------------------------------------------------------------
// Scratch (no cudaMalloc allowed)
// ---------------------------------------------------------------------------
__device__ float g_t1[(size_t)NN * HID_DIM];    // x @ W1
__device__ float g_agg1[(size_t)NN * HID_DIM];  // A @ t1
__device__ float g_t2[(size_t)NN * LAT_DIM];    // relu(agg1+b1) @ W2
__device__ int   g_deg[NN];
__device__ int   g_off[NN + 1];
__device__ int   g_cur[NN];
__device__ int2  g_edge[NE];                    // dst-sorted (src, val_bits)
// W transposed to [N][K=128], bf16 hi/lo split
__device__ __nv_bfloat16 g_w1hi[128 * 128];
__device__ __nv_bfloat16 g_w1lo[128 * 128];
__device__ __nv_bfloat16 g_w2hi[64 * 128];
__device__ __nv_bfloat16 g_w2lo[64 * 128];

// ---------------------------------------------------------------------------
// warp-MMA helpers (baseline PTX, works on plain compute_103 target)
// ---------------------------------------------------------------------------
__device__ __forceinline__ uint32_t smem_u32(const void* p) {
    uint32_t a;
    asm("{ .reg .u64 t; cvta.to.shared.u64 t, %1; cvt.u32.u64 %0, t; }" : "=r"(a) : "l"(p));
    return a;
}
__device__ __forceinline__ void ldsm4(uint32_t addr, uint32_t& r0, uint32_t& r1,
                                      uint32_t& r2, uint32_t& r3) {
    asm volatile("ldmatrix.sync.aligned.m8n8.x4.shared.b16 {%0,%1,%2,%3}, [%4];"
                 : "=r"(r0), "=r"(r1), "=r"(r2), "=r"(r3) : "r"(addr));
}
__device__ __forceinline__ void mma16816(float* d, const uint32_t* a, const uint32_t* b) {
    asm volatile("mma.sync.aligned.m16n8k16.row.col.f32.bf16.bf16.f32 "
                 "{%0,%1,%2,%3}, {%4,%5,%6,%7}, {%8,%9}, {%0,%1,%2,%3};"
                 : "+f"(d[0]), "+f"(d[1]), "+f"(d[2]), "+f"(d[3])
                 : "r"(a[0]), "r"(a[1]), "r"(a[2]), "r"(a[3]), "r"(b[0]), "r"(b[1]));
}
__device__ __forceinline__ uint32_t pack_bf16x2(__nv_bfloat16 a, __nv_bfloat16 b) {
    return (uint32_t)__bfloat16_as_ushort(a) | ((uint32_t)__bfloat16_as_ushort(b) << 16);
}

// ---------------------------------------------------------------------------
// prep_w: W[k][n] row-major -> Wt[n][k] bf16 hi/lo
// ---------------------------------------------------------------------------
__global__ void __launch_bounds__(256) prep_w(const float* __restrict__ W, int N,
                                              __nv_bfloat16* __restrict__ hi,
                                              __nv_bfloat16* __restrict__ lo) {
    const int total = 128 * N;
    for (int idx = blockIdx.x * blockDim.x + threadIdx.x; idx < total;
         idx += gridDim.x * blockDim.x) {
        const int k = idx / N, n = idx % N;
        const float v = W[idx];
        const __nv_bfloat16 h = __float2bfloat16(v);
        const __nv_bfloat16 l = __float2bfloat16(v - __bfloat162float(h));
        hi[n * 128 + k] = h;
        lo[n * 128 + k] = l;
    }
}

// ---------------------------------------------------------------------------
// HMMA GEMM: out[128 rows, N] = X[rows,128] @ Wt  (bf16-split, 3 passes)
// 256 threads; warp w -> 32x(N/2) output tile; K=128 resident in smem.
// Padded rows (stride 136 bf16 = 272B) => conflict-free ldmatrix.
// ---------------------------------------------------------------------------
template <int N_DIM, bool RELU_BIAS>
__global__ void __launch_bounds__(256) gemm_mma(const float* __restrict__ X,
                                                const float* __restrict__ BIAS,
                                                const __nv_bfloat16* __restrict__ WHI,
                                                const __nv_bfloat16* __restrict__ WLO,
                                                float* __restrict__ out) {
    extern __shared__ __nv_bfloat16 sm[];
    constexpr int LDS = 136;                 // padded row stride (elements)
    constexpr int AHI = 0;
    constexpr int ALO = 128 * LDS;
    constexpr int BHI = 2 * 128 * LDS;
    constexpr int BLO = BHI + N_DIM * LDS;
    constexpr int WN = N_DIM / 2;            // warp n-extent
    constexpr int NT = WN / 8;               // n-tiles per warp

    const int tid = threadIdx.x;
    const int wid = tid >> 5, lane = tid & 31;
    const int row0 = blockIdx.x * 128;
    const uint32_t smb = smem_u32(sm);

    // copy Wt hi/lo into padded smem rows (16B chunks)
    {
        const uint4* sh = (const uint4*)WHI;
        const uint4* sl = (const uint4*)WLO;
        for (int i = tid; i < N_DIM * 16; i += 256) {
            const int r = i >> 4, c = i & 15;
            *(uint4*)(sm + BHI + r * LDS + c * 8) = sh[i];
            *(uint4*)(sm + BLO + r * LDS + c * 8) = sl[i];
        }
    }

    // load + (optional bias/relu) + hi/lo split-convert the A tile
    {
        const int r = tid >> 1;
        const int kh = (tid & 1) * 64;
        const bool ok = (row0 + r) < NN;
        uint32_t* ahi = (uint32_t*)(sm + AHI + r * LDS + kh);
        uint32_t* alo = (uint32_t*)(sm + ALO + r * LDS + kh);
#pragma unroll
        for (int i = 0; i < 16; i++) {
            float4 v = make_float4(0.f, 0.f, 0.f, 0.f);
            if (ok) {
                v = *(const float4*)(X + (size_t)(row0 + r) * 128 + kh + i * 4);
                if (RELU_BIAS) {
                    const float4 bv = *(const float4*)(BIAS + kh + i * 4);
                    v.x = fmaxf(v.x + bv.x, 0.f);
                    v.y = fmaxf(v.y + bv.y, 0.f);
                    v.z = fmaxf(v.z + bv.z, 0.f);
                    v.w = fmaxf(v.w + bv.w, 0.f);
                }
            }
            const __nv_bfloat16 h0 = __float2bfloat16(v.x), h1 = __float2bfloat16(v.y);
            const __nv_bfloat16 h2 = __float2bfloat16(v.z), h3 = __float2bfloat16(v.w);
            const __nv_bfloat16 l0 = __float2bfloat16(v.x - __bfloat162float(h0));
            const __nv_bfloat16 l1 = __float2bfloat16(v.y - __bfloat162float(h1));
            const __nv_bfloat16 l2 = __float2bfloat16(v.z - __bfloat162float(h2));
            const __nv_bfloat16 l3 = __float2bfloat16(v.w - __bfloat162float(h3));
            ahi[i * 2] = pack_bf16x2(h0, h1);
            ahi[i * 2 + 1] = pack_bf16x2(h2, h3);
            alo[i * 2] = pack_bf16x2(l0, l1);
            alo[i * 2 + 1] = pack_bf16x2(l2, l3);
        }
    }
    __syncthreads();

    const int m0 = (wid & 3) * 32;
    const int n0 = (wid >> 2) * WN;

    float acc[2][NT][4];
#pragma unroll
    for (int mt = 0; mt < 2; mt++)
#pragma unroll
        for (int nt = 0; nt < NT; nt++)
#pragma unroll
            for (int j = 0; j < 4; j++) acc[mt][nt][j] = 0.f;

#pragma unroll
    for (int p = 0; p < 3; p++) {
        const int aoff = (p == 2) ? ALO : AHI;
        const int boff = (p == 1) ? BLO : BHI;
        const uint32_t abase = smb + 2 * aoff;
        const uint32_t bbase = smb + 2 * boff;
#pragma unroll
        for (int ks = 0; ks < 8; ks++) {
            uint32_t af[2][4];
#pragma unroll
            for (int mt = 0; mt < 2; mt++) {
                const int r = m0 + mt * 16 + (lane & 7) + ((lane >> 3) & 1) * 8;
                const int kk = ks * 16 + (lane >> 4) * 8;
                ldsm4(abase + (uint32_t)(r * LDS + kk) * 2,
                      af[mt][0], af[mt][1], af[mt][2], af[mt][3]);
            }
            uint32_t bf[NT][2];
#pragma unroll
            for (int np = 0; np < NT / 2; np++) {
                const int r = n0 + np * 16 + (lane >> 4) * 8 + (lane & 7);
                const int kk = ks * 16 + ((lane >> 3) & 1) * 8;
                uint32_t t0, t1, t2, t3;
                ldsm4(bbase + (uint32_t)(r * LDS + kk) * 2, t0, t1, t2, t3);
                bf[2 * np][0] = t0; bf[2 * np][1] = t1;
                bf[2 * np + 1][0] = t2; bf[2 * np + 1][1] = t3;
            }
#pragma unroll
            for (int mt = 0; mt < 2; mt++)
#pragma unroll
                for (int nt = 0; nt < NT; nt++) mma16816(acc[mt][nt], af[mt], bf[nt]);
        }
    }

    // epilogue: D frag -> global (lane l owns rows l/4, l/4+8; cols 2(l%4))
#pragma unroll
    for (int mt = 0; mt < 2; mt++) {
        const int r = row0 + m0 + mt * 16 + (lane >> 2);
#pragma unroll
        for (int nt = 0; nt < NT; nt++) {
            const int c = n0 + nt * 8 + (lane & 3) * 2;
            if (r < NN)
                *(float2*)(out + (size_t)r * N_DIM + c) =
                    make_float2(acc[mt][nt][0], acc[mt][nt][1]);
            if (r + 8 < NN)
                *(float2*)(out + (size_t)(r + 8) * N_DIM + c) =
                    make_float2(acc[mt][nt][2], acc[mt][nt][3]);
        }
    }
}

// ---------------------------------------------------------------------------
// CSR build: zero -> histogram -> scan -> scatter
// ---------------------------------------------------------------------------
__global__ void __launch_bounds__(256) zero_deg() {
    const int i = blockIdx.x * blockDim.x + threadIdx.x;
    if (i < NN) g_deg[i] = 0;
}
__global__ void __launch_bounds__(256) hist_kernel(const int* __restrict__ dst, int E) {
    const int i = blockIdx.x * blockDim.x + threadIdx.x;
    if (i < E) atomicAdd(&g_deg[dst[i]], 1);
}
__global__ void __launch_bounds__(1024) scan_kernel(int E) {
    __shared__ int ssum[1024];
    const int t = threadIdx.x;
    const int CH = (NN + 1023) / 1024;
    const int lo = t * CH, hi = min(lo + CH, NN);
    int s = 0;
    for (int i = lo; i < hi; i++) s += g_deg[i];
    const int mysum = s;
    ssum[t] = s;
    __syncthreads();
    for (int d = 1; d < 1024; d <<= 1) {
        int add = (t >= d) ? ssum[t - d] : 0;
        __syncthreads();
        ssum[t] += add;
        __syncthreads();
    }
    int run = ssum[t] - mysum;
    for (int i = lo; i < hi; i++) {
        g_off[i] = run;
        g_cur[i] = run;
        run += g_deg[i];
    }
    if (t == 1023) g_off[NN] = run;
}
__global__ void __launch_bounds__(256) scatter_kernel(const int* __restrict__ src,
                                                      const int* __restrict__ dst,
                                                      const float* __restrict__ vals, int E) {
    const int i = blockIdx.x * blockDim.x + threadIdx.x;
    if (i < E) {
        const int d = dst[i];
        const int p = atomicAdd(&g_cur[d], 1);
        g_edge[p] = make_int2(src[i], __float_as_int(vals[i]));
    }
}

// ---------------------------------------------------------------------------
// gather SpMM: one warp per dst row (no atomics)
// ---------------------------------------------------------------------------
__global__ void __launch_bounds__(256) spmm_gather128(const float* __restrict__ X,
                                                      float* __restrict__ Y) {
    const int lane = threadIdx.x & 31;
    const int row = (blockIdx.x * blockDim.x + threadIdx.x) >> 5;
    if (row >= NN) return;
    const int beg = g_off[row], end = g_off[row + 1];
    const float4* Xv = (const float4*)X;
    float4 acc = make_float4(0.f, 0.f, 0.f, 0.f);
    int e = beg;
    for (; e + 4 <= end; e += 4) {
        const int2 e0 = g_edge[e], e1 = g_edge[e + 1], e2 = g_edge[e + 2], e3 = g_edge[e + 3];
        const float4 x0 = Xv[(size_t)e0.x * 32 + lane];
        const float4 x1 = Xv[(size_t)e1.x * 32 + lane];
        const float4 x2 = Xv[(size_t)e2.x * 32 + lane];
        const float4 x3 = Xv[(size_t)e3.x * 32 + lane];
        const float v0 = __int_as_float(e0.y), v1 = __int_as_float(e1.y);
        const float v2 = __int_as_float(e2.y), v3 = __int_as_float(e3.y);
        acc.x += v0 * x0.x + v1 * x1.x + v2 * x2.x + v3 * x3.x;
        acc.y += v0 * x0.y + v1 * x1.y + v2 * x2.y + v3 * x3.y;
        acc.z += v0 * x0.z + v1 * x1.z + v2 * x2.z + v3 * x3.z;
        acc.w += v0 * x0.w + v1 * x1.w + v2 * x2.w + v3 * x3.w;
    }
    for (; e < end; e++) {
        const int2 ee = g_edge[e];
        const float4 xv = Xv[(size_t)ee.x * 32 + lane];
        const float v = __int_as_float(ee.y);
        acc.x += v * xv.x; acc.y += v * xv.y; acc.z += v * xv.z; acc.w += v * xv.w;
    }
    ((float4*)Y)[(size_t)row * 32 + lane] = acc;
}

__global__ void __launch_bounds__(256) spmm_gather64(const float* __restrict__ X,
                                                     const float* __restrict__ B2,
                                                     float* __restrict__ Y) {
    const int lane = threadIdx.x & 31;
    const int row = (blockIdx.x * blockDim.x + threadIdx.x) >> 5;
    if (row >= NN) return;
    const int beg = g_off[row], end = g_off[row + 1];
    const float2* Xv = (const float2*)X;
    float2 acc = make_float2(0.f, 0.f);
    int e = beg;
    for (; e + 4 <= end; e += 4) {
        const int2 e0 = g_edge[e], e1 = g_edge[e + 1], e2 = g_edge[e + 2], e3 = g_edge[e + 3];
        const float2 x0 = Xv[(size_t)e0.x * 32 + lane];
        const float2 x1 = Xv[(size_t)e1.x * 32 + lane];
        const float2 x2 = Xv[(size_t)e2.x * 32 + lane];
        const float2 x3 = Xv[(size_t)e3.x * 32 + lane];
        const float v0 = __int_as_float(e0.y), v1 = __int_as_float(e1.y);
        const float v2 = __int_as_float(e2.y), v3 = __int_as_float(e3.y);
        acc.x += v0 * x0.x + v1 * x1.x + v2 * x2.x + v3 * x3.x;
        acc.y += v0 * x0.y + v1 * x1.y + v2 * x2.y + v3 * x3.y;
    }
    for (; e < end; e++) {
        const int2 ee = g_edge[e];
        const float2 xv = Xv[(size_t)ee.x * 32 + lane];
        const float v = __int_as_float(ee.y);
        acc.x += v * xv.x; acc.y += v * xv.y;
    }
    const float2 bv = *(const float2*)(B2 + lane * 2);
    acc.x += bv.x; acc.y += bv.y;
    ((float2*)Y)[(size_t)row * 32 + lane] = acc;
}

// ---------------------------------------------------------------------------
extern "C" void kernel_launch(void* const* d_in, const int* in_sizes, int n_in,
                              void* d_out, int out_size) {
    const float* x  = (const float*)d_in[0];
    const int*   es = (const int*)d_in[1];
    const int*   ed = (const int*)d_in[2];
    const float* ev = (const float*)d_in[3];
    const float* W1 = (const float*)d_in[4];
    const float* b1 = (const float*)d_in[5];
    const float* W2 = (const float*)d_in[6];
    const float* b2 = (const float*)d_in[7];
    float* out = (float*)d_out;
    const int E = in_sizes[1];

    float *t1, *agg1, *t2;
    __nv_bfloat16 *w1hi, *w1lo, *w2hi, *w2lo;
    cudaGetSymbolAddress((void**)&t1, g_t1);
    cudaGetSymbolAddress((void**)&agg1, g_agg1);
    cudaGetSymbolAddress((void**)&t2, g_t2);
    cudaGetSymbolAddress((void**)&w1hi, g_w1hi);
    cudaGetSymbolAddress((void**)&w1lo, g_w1lo);
    cudaGetSymbolAddress((void**)&w2hi, g_w2hi);
    cudaGetSymbolAddress((void**)&w2lo, g_w2lo);

    constexpr int SM1 = (2 * 128 + 2 * 128) * 136 * 2;  // 139,264 B
    constexpr int SM2 = (2 * 128 + 2 * 64) * 136 * 2;   // 104,448 B
    cudaFuncSetAttribute(gemm_mma<128, false>, cudaFuncAttributeMaxDynamicSharedMemorySize, SM1);
    cudaFuncSetAttribute(gemm_mma<64, true>, cudaFuncAttributeMaxDynamicSharedMemorySize, SM2);

    const int eb = (E + 255) / 256;
    const int gemm_blocks = (NN + 127) / 128;       // 782
    const int spmm_blocks = (NN * 32 + 255) / 256;  // warp per row

    // CSR build + W conversion (independent of GEMM inputs)
    zero_deg<<<(NN + 255) / 256, 256>>>();
    prep_w<<<64, 256>>>(W1, 128, w1hi, w1lo);
    prep_w<<<32, 256>>>(W2, 64, w2hi, w2lo);
    hist_kernel<<<eb, 256>>>(ed, E);
    scan_kernel<<<1, 1024>>>(E);
    scatter_kernel<<<eb, 256>>>(es, ed, ev, E);

    // t1 = x @ W1  (HMMA bf16-split)
    gemm_mma<128, false><<<gemm_blocks, 256, SM1>>>(x, nullptr, w1hi, w1lo, t1);
    // agg1 = A @ t1
    spmm_gather128<<<spmm_blocks, 256>>>(t1, agg1);
    // t2 = relu(agg1 + b1) @ W2  (bias+relu fused into A conversion)
    gemm_mma<64, true><<<gemm_blocks, 256, SM2>>>(agg1, b1, w2hi, w2lo, t2);
    // out = A @ t2 + b2
    spmm_gather64<<<spmm_blocks, 256>>>(t2, b2, out);
}

// round 5
// speedup vs baseline: 1.1829x; 1.0546x over previous
#include <cuda_runtime.h>
#include <cuda_bf16.h>
#include <cuda_fp16.h>
#include <cstdint>
#include <cstddef>

#define NN 100000
#define NE 1600000
#define IN_DIM 128
#define HID_DIM 128
#define LAT_DIM 64

// ---------------------------------------------------------------------------
// Scratch (no cudaMalloc allowed)
// ---------------------------------------------------------------------------
__device__ __half g_t1[(size_t)NN * HID_DIM];   // x @ W1           (fp16)
__device__ float  g_agg1[(size_t)NN * HID_DIM]; // A @ t1           (fp32)
__device__ __half g_t2[(size_t)NN * LAT_DIM];   // relu(agg1+b1)@W2 (fp16)
__device__ int    g_deg[NN];
__device__ int    g_off[NN + 1];
__device__ int    g_cur[NN];
__device__ int2   g_edge[NE];                   // dst-sorted (src, val_bits)
// W transposed to [N][K=128], bf16 hi/lo split
__device__ __nv_bfloat16 g_w1hi[128 * 128];
__device__ __nv_bfloat16 g_w1lo[128 * 128];
__device__ __nv_bfloat16 g_w2hi[64 * 128];
__device__ __nv_bfloat16 g_w2lo[64 * 128];

// ---------------------------------------------------------------------------
// warp-MMA helpers (baseline PTX, works on plain compute_103 target)
// ---------------------------------------------------------------------------
__device__ __forceinline__ uint32_t smem_u32(const void* p) {
    uint32_t a;
    asm("{ .reg .u64 t; cvta.to.shared.u64 t, %1; cvt.u32.u64 %0, t; }" : "=r"(a) : "l"(p));
    return a;
}
__device__ __forceinline__ void ldsm4(uint32_t addr, uint32_t& r0, uint32_t& r1,
                                      uint32_t& r2, uint32_t& r3) {
    asm volatile("ldmatrix.sync.aligned.m8n8.x4.shared.b16 {%0,%1,%2,%3}, [%4];"
                 : "=r"(r0), "=r"(r1), "=r"(r2), "=r"(r3) : "r"(addr));
}
__device__ __forceinline__ void mma16816(float* d, const uint32_t* a, const uint32_t* b) {
    asm volatile("mma.sync.aligned.m16n8k16.row.col.f32.bf16.bf16.f32 "
                 "{%0,%1,%2,%3}, {%4,%5,%6,%7}, {%8,%9}, {%0,%1,%2,%3};"
                 : "+f"(d[0]), "+f"(d[1]), "+f"(d[2]), "+f"(d[3])
                 : "r"(a[0]), "r"(a[1]), "r"(a[2]), "r"(a[3]), "r"(b[0]), "r"(b[1]));
}
__device__ __forceinline__ uint32_t pack_bf16x2(__nv_bfloat16 a, __nv_bfloat16 b) {
    return (uint32_t)__bfloat16_as_ushort(a) | ((uint32_t)__bfloat16_as_ushort(b) << 16);
}

// ---------------------------------------------------------------------------
// prep_w: W[k][n] row-major -> Wt[n][k] bf16 hi/lo
// ---------------------------------------------------------------------------
__global__ void __launch_bounds__(256) prep_w(const float* __restrict__ W, int N,
                                              __nv_bfloat16* __restrict__ hi,
                                              __nv_bfloat16* __restrict__ lo) {
    const int total = 128 * N;
    for (int idx = blockIdx.x * blockDim.x + threadIdx.x; idx < total;
         idx += gridDim.x * blockDim.x) {
        const int k = idx / N, n = idx % N;
        const float v = W[idx];
        const __nv_bfloat16 h = __float2bfloat16(v);
        const __nv_bfloat16 l = __float2bfloat16(v - __bfloat162float(h));
        hi[n * 128 + k] = h;
        lo[n * 128 + k] = l;
    }
}

// ---------------------------------------------------------------------------
// HMMA GEMM: out16[128 rows, N] = X[rows,128] @ Wt  (bf16-split, 3 passes)
// 256 threads; warp w -> 32x(N/2) output tile; K=128 resident in smem.
// Epilogue writes fp16 (feeds the gather SpMM at half the traffic).
// ---------------------------------------------------------------------------
template <int N_DIM, bool RELU_BIAS>
__global__ void __launch_bounds__(256) gemm_mma(const float* __restrict__ X,
                                                const float* __restrict__ BIAS,
                                                const __nv_bfloat16* __restrict__ WHI,
                                                const __nv_bfloat16* __restrict__ WLO,
                                                __half* __restrict__ out) {
    extern __shared__ __nv_bfloat16 sm[];
    constexpr int LDS = 136;                 // padded row stride (elements)
    constexpr int AHI = 0;
    constexpr int ALO = 128 * LDS;
    constexpr int BHI = 2 * 128 * LDS;
    constexpr int BLO = BHI + N_DIM * LDS;
    constexpr int WN = N_DIM / 2;            // warp n-extent
    constexpr int NT = WN / 8;               // n-tiles per warp

    const int tid = threadIdx.x;
    const int wid = tid >> 5, lane = tid & 31;
    const int row0 = blockIdx.x * 128;
    const uint32_t smb = smem_u32(sm);

    // copy Wt hi/lo into padded smem rows (16B chunks)
    {
        const uint4* sh = (const uint4*)WHI;
        const uint4* sl = (const uint4*)WLO;
        for (int i = tid; i < N_DIM * 16; i += 256) {
            const int r = i >> 4, c = i & 15;
            *(uint4*)(sm + BHI + r * LDS + c * 8) = sh[i];
            *(uint4*)(sm + BLO + r * LDS + c * 8) = sl[i];
        }
    }

    // load + (optional bias/relu) + hi/lo split-convert the A tile
    {
        const int r = tid >> 1;
        const int kh = (tid & 1) * 64;
        const bool ok = (row0 + r) < NN;
        uint32_t* ahi = (uint32_t*)(sm + AHI + r * LDS + kh);
        uint32_t* alo = (uint32_t*)(sm + ALO + r * LDS + kh);
#pragma unroll
        for (int i = 0; i < 16; i++) {
            float4 v = make_float4(0.f, 0.f, 0.f, 0.f);
            if (ok) {
                v = *(const float4*)(X + (size_t)(row0 + r) * 128 + kh + i * 4);
                if (RELU_BIAS) {
                    const float4 bv = *(const float4*)(BIAS + kh + i * 4);
                    v.x = fmaxf(v.x + bv.x, 0.f);
                    v.y = fmaxf(v.y + bv.y, 0.f);
                    v.z = fmaxf(v.z + bv.z, 0.f);
                    v.w = fmaxf(v.w + bv.w, 0.f);
                }
            }
            const __nv_bfloat16 h0 = __float2bfloat16(v.x), h1 = __float2bfloat16(v.y);
            const __nv_bfloat16 h2 = __float2bfloat16(v.z), h3 = __float2bfloat16(v.w);
            const __nv_bfloat16 l0 = __float2bfloat16(v.x - __bfloat162float(h0));
            const __nv_bfloat16 l1 = __float2bfloat16(v.y - __bfloat162float(h1));
            const __nv_bfloat16 l2 = __float2bfloat16(v.z - __bfloat162float(h2));
            const __nv_bfloat16 l3 = __float2bfloat16(v.w - __bfloat162float(h3));
            ahi[i * 2] = pack_bf16x2(h0, h1);
            ahi[i * 2 + 1] = pack_bf16x2(h2, h3);
            alo[i * 2] = pack_bf16x2(l0, l1);
            alo[i * 2 + 1] = pack_bf16x2(l2, l3);
        }
    }
    __syncthreads();

    const int m0 = (wid & 3) * 32;
    const int n0 = (wid >> 2) * WN;

    float acc[2][NT][4];
#pragma unroll
    for (int mt = 0; mt < 2; mt++)
#pragma unroll
        for (int nt = 0; nt < NT; nt++)
#pragma unroll
            for (int j = 0; j < 4; j++) acc[mt][nt][j] = 0.f;

#pragma unroll
    for (int p = 0; p < 3; p++) {
        const int aoff = (p == 2) ? ALO : AHI;
        const int boff = (p == 1) ? BLO : BHI;
        const uint32_t abase = smb + 2 * aoff;
        const uint32_t bbase = smb + 2 * boff;
#pragma unroll
        for (int ks = 0; ks < 8; ks++) {
            uint32_t af[2][4];
#pragma unroll
            for (int mt = 0; mt < 2; mt++) {
                const int r = m0 + mt * 16 + (lane & 7) + ((lane >> 3) & 1) * 8;
                const int kk = ks * 16 + (lane >> 4) * 8;
                ldsm4(abase + (uint32_t)(r * LDS + kk) * 2,
                      af[mt][0], af[mt][1], af[mt][2], af[mt][3]);
            }
            uint32_t bf[NT][2];
#pragma unroll
            for (int np = 0; np < NT / 2; np++) {
                const int r = n0 + np * 16 + (lane >> 4) * 8 + (lane & 7);
                const int kk = ks * 16 + ((lane >> 3) & 1) * 8;
                uint32_t t0, t1, t2, t3;
                ldsm4(bbase + (uint32_t)(r * LDS + kk) * 2, t0, t1, t2, t3);
                bf[2 * np][0] = t0; bf[2 * np][1] = t1;
                bf[2 * np + 1][0] = t2; bf[2 * np + 1][1] = t3;
            }
#pragma unroll
            for (int mt = 0; mt < 2; mt++)
#pragma unroll
                for (int nt = 0; nt < NT; nt++) mma16816(acc[mt][nt], af[mt], bf[nt]);
        }
    }

    // epilogue: D frag -> global fp16 (lane l owns rows l/4, l/4+8; cols 2(l%4))
#pragma unroll
    for (int mt = 0; mt < 2; mt++) {
        const int r = row0 + m0 + mt * 16 + (lane >> 2);
#pragma unroll
        for (int nt = 0; nt < NT; nt++) {
            const int c = n0 + nt * 8 + (lane & 3) * 2;
            if (r < NN)
                *(__half2*)(out + (size_t)r * N_DIM + c) =
                    __floats2half2_rn(acc[mt][nt][0], acc[mt][nt][1]);
            if (r + 8 < NN)
                *(__half2*)(out + (size_t)(r + 8) * N_DIM + c) =
                    __floats2half2_rn(acc[mt][nt][2], acc[mt][nt][3]);
        }
    }
}

// ---------------------------------------------------------------------------
// CSR build: zero -> histogram -> scan -> scatter
// ---------------------------------------------------------------------------
__global__ void __launch_bounds__(256) zero_deg() {
    const int i = blockIdx.x * blockDim.x + threadIdx.x;
    if (i < NN) g_deg[i] = 0;
}
__global__ void __launch_bounds__(256) hist_kernel(const int* __restrict__ dst, int E) {
    const int i = blockIdx.x * blockDim.x + threadIdx.x;
    if (i < E) atomicAdd(&g_deg[dst[i]], 1);
}
__global__ void __launch_bounds__(1024) scan_kernel(int E) {
    __shared__ int ssum[1024];
    const int t = threadIdx.x;
    const int CH = (NN + 1023) / 1024;
    const int lo = t * CH, hi = min(lo + CH, NN);
    int s = 0;
    for (int i = lo; i < hi; i++) s += g_deg[i];
    const int mysum = s;
    ssum[t] = s;
    __syncthreads();
    for (int d = 1; d < 1024; d <<= 1) {
        int add = (t >= d) ? ssum[t - d] : 0;
        __syncthreads();
        ssum[t] += add;
        __syncthreads();
    }
    int run = ssum[t] - mysum;
    for (int i = lo; i < hi; i++) {
        g_off[i] = run;
        g_cur[i] = run;
        run += g_deg[i];
    }
    if (t == 1023) g_off[NN] = run;
}
__global__ void __launch_bounds__(256) scatter_kernel(const int* __restrict__ src,
                                                      const int* __restrict__ dst,
                                                      const float* __restrict__ vals, int E) {
    const int i = blockIdx.x * blockDim.x + threadIdx.x;
    if (i < E) {
        const int d = dst[i];
        const int p = atomicAdd(&g_cur[d], 1);
        g_edge[p] = make_int2(src[i], __float_as_int(vals[i]));
    }
}

// ---------------------------------------------------------------------------
// gather SpMM (fp16 operand, fp32 accumulate): one warp per dst row
// ---------------------------------------------------------------------------
__global__ void __launch_bounds__(256) spmm_gather128(const __half* __restrict__ X,
                                                      float* __restrict__ Y) {
    const int lane = threadIdx.x & 31;
    const int row = (blockIdx.x * blockDim.x + threadIdx.x) >> 5;
    if (row >= NN) return;
    const int beg = g_off[row], end = g_off[row + 1];
    const uint2* Xv = (const uint2*)X;  // uint2 = 4 halves; row = 32 uint2

    float4 acc = make_float4(0.f, 0.f, 0.f, 0.f);
    int e = beg;
    for (; e + 4 <= end; e += 4) {
        const int2 e0 = g_edge[e], e1 = g_edge[e + 1], e2 = g_edge[e + 2], e3 = g_edge[e + 3];
        const uint2 x0 = Xv[(size_t)e0.x * 32 + lane];
        const uint2 x1 = Xv[(size_t)e1.x * 32 + lane];
        const uint2 x2 = Xv[(size_t)e2.x * 32 + lane];
        const uint2 x3 = Xv[(size_t)e3.x * 32 + lane];
        const float v0 = __int_as_float(e0.y), v1 = __int_as_float(e1.y);
        const float v2 = __int_as_float(e2.y), v3 = __int_as_float(e3.y);
        float2 a, b;
        a = __half22float2(*(const __half2*)&x0.x); b = __half22float2(*(const __half2*)&x0.y);
        acc.x += v0 * a.x; acc.y += v0 * a.y; acc.z += v0 * b.x; acc.w += v0 * b.y;
        a = __half22float2(*(const __half2*)&x1.x); b = __half22float2(*(const __half2*)&x1.y);
        acc.x += v1 * a.x; acc.y += v1 * a.y; acc.z += v1 * b.x; acc.w += v1 * b.y;
        a = __half22float2(*(const __half2*)&x2.x); b = __half22float2(*(const __half2*)&x2.y);
        acc.x += v2 * a.x; acc.y += v2 * a.y; acc.z += v2 * b.x; acc.w += v2 * b.y;
        a = __half22float2(*(const __half2*)&x3.x); b = __half22float2(*(const __half2*)&x3.y);
        acc.x += v3 * a.x; acc.y += v3 * a.y; acc.z += v3 * b.x; acc.w += v3 * b.y;
    }
    for (; e < end; e++) {
        const int2 ee = g_edge[e];
        const uint2 xv = Xv[(size_t)ee.x * 32 + lane];
        const float v = __int_as_float(ee.y);
        const float2 a = __half22float2(*(const __half2*)&xv.x);
        const float2 b = __half22float2(*(const __half2*)&xv.y);
        acc.x += v * a.x; acc.y += v * a.y; acc.z += v * b.x; acc.w += v * b.y;
    }
    ((float4*)Y)[(size_t)row * 32 + lane] = acc;
}

__global__ void __launch_bounds__(256) spmm_gather64(const __half* __restrict__ X,
                                                     const float* __restrict__ B2,
                                                     float* __restrict__ Y) {
    const int lane = threadIdx.x & 31;
    const int row = (blockIdx.x * blockDim.x + threadIdx.x) >> 5;
    if (row >= NN) return;
    const int beg = g_off[row], end = g_off[row + 1];
    const __half2* Xv = (const __half2*)X;  // row = 32 half2

    float2 acc = make_float2(0.f, 0.f);
    int e = beg;
    for (; e + 4 <= end; e += 4) {
        const int2 e0 = g_edge[e], e1 = g_edge[e + 1], e2 = g_edge[e + 2], e3 = g_edge[e + 3];
        const float2 x0 = __half22float2(Xv[(size_t)e0.x * 32 + lane]);
        const float2 x1 = __half22float2(Xv[(size_t)e1.x * 32 + lane]);
        const float2 x2 = __half22float2(Xv[(size_t)e2.x * 32 + lane]);
        const float2 x3 = __half22float2(Xv[(size_t)e3.x * 32 + lane]);
        const float v0 = __int_as_float(e0.y), v1 = __int_as_float(e1.y);
        const float v2 = __int_as_float(e2.y), v3 = __int_as_float(e3.y);
        acc.x += v0 * x0.x + v1 * x1.x + v2 * x2.x + v3 * x3.x;
        acc.y += v0 * x0.y + v1 * x1.y + v2 * x2.y + v3 * x3.y;
    }
    for (; e < end; e++) {
        const int2 ee = g_edge[e];
        const float2 xv = __half22float2(Xv[(size_t)ee.x * 32 + lane]);
        const float v = __int_as_float(ee.y);
        acc.x += v * xv.x; acc.y += v * xv.y;
    }
    const float2 bv = *(const float2*)(B2 + lane * 2);
    acc.x += bv.x; acc.y += bv.y;
    ((float2*)Y)[(size_t)row * 32 + lane] = acc;
}

// ---------------------------------------------------------------------------
extern "C" void kernel_launch(void* const* d_in, const int* in_sizes, int n_in,
                              void* d_out, int out_size) {
    const float* x  = (const float*)d_in[0];
    const int*   es = (const int*)d_in[1];
    const int*   ed = (const int*)d_in[2];
    const float* ev = (const float*)d_in[3];
    const float* W1 = (const float*)d_in[4];
    const float* b1 = (const float*)d_in[5];
    const float* W2 = (const float*)d_in[6];
    const float* b2 = (const float*)d_in[7];
    float* out = (float*)d_out;
    const int E = in_sizes[1];

    __half *t1, *t2;
    float* agg1;
    __nv_bfloat16 *w1hi, *w1lo, *w2hi, *w2lo;
    cudaGetSymbolAddress((void**)&t1, g_t1);
    cudaGetSymbolAddress((void**)&agg1, g_agg1);
    cudaGetSymbolAddress((void**)&t2, g_t2);
    cudaGetSymbolAddress((void**)&w1hi, g_w1hi);
    cudaGetSymbolAddress((void**)&w1lo, g_w1lo);
    cudaGetSymbolAddress((void**)&w2hi, g_w2hi);
    cudaGetSymbolAddress((void**)&w2lo, g_w2lo);

    constexpr int SM1 = (2 * 128 + 2 * 128) * 136 * 2;  // 139,264 B
    constexpr int SM2 = (2 * 128 + 2 * 64) * 136 * 2;   // 104,448 B
    cudaFuncSetAttribute(gemm_mma<128, false>, cudaFuncAttributeMaxDynamicSharedMemorySize, SM1);
    cudaFuncSetAttribute(gemm_mma<64, true>, cudaFuncAttributeMaxDynamicSharedMemorySize, SM2);

    const int eb = (E + 255) / 256;
    const int gemm_blocks = (NN + 127) / 128;       // 782
    const int spmm_blocks = (NN * 32 + 255) / 256;  // warp per row

    // CSR build + W conversion (independent of GEMM inputs)
    zero_deg<<<(NN + 255) / 256, 256>>>();
    prep_w<<<64, 256>>>(W1, 128, w1hi, w1lo);
    prep_w<<<32, 256>>>(W2, 64, w2hi, w2lo);
    hist_kernel<<<eb, 256>>>(ed, E);
    scan_kernel<<<1, 1024>>>(E);
    scatter_kernel<<<eb, 256>>>(es, ed, ev, E);

    // t1 = x @ W1  (HMMA bf16-split, fp16 out)
    gemm_mma<128, false><<<gemm_blocks, 256, SM1>>>(x, nullptr, w1hi, w1lo, t1);
    // agg1 = A @ t1  (fp16 gather, fp32 accumulate)
    spmm_gather128<<<spmm_blocks, 256>>>(t1, agg1);
    // t2 = relu(agg1 + b1) @ W2  (bias+relu fused into A conversion, fp16 out)
    gemm_mma<64, true><<<gemm_blocks, 256, SM2>>>(agg1, b1, w2hi, w2lo, t2);
    // out = A @ t2 + b2  (fp16 gather, fp32 accumulate + bias)
    spmm_gather64<<<spmm_blocks, 256>>>(t2, b2, out);
}

// round 6
// speedup vs baseline: 1.2420x; 1.0500x over previous
#include <cuda_runtime.h>
#include <cuda_bf16.h>
#include <cuda_fp16.h>
#include <cstdint>
#include <cstddef>

#define NN 100000
#define NE 1600000
#define IN_DIM 128
#define HID_DIM 128
#define LAT_DIM 64

// ---------------------------------------------------------------------------
// Scratch (no cudaMalloc allowed)
// ---------------------------------------------------------------------------
__device__ __half g_t1[(size_t)NN * HID_DIM];   // x @ W1           (fp16)
__device__ float  g_agg1[(size_t)NN * HID_DIM]; // A @ t1           (fp32)
__device__ __half g_t2[(size_t)NN * LAT_DIM];   // relu(agg1+b1)@W2 (fp16)
__device__ int    g_deg[NN];
__device__ int    g_off[NN + 1];
__device__ int    g_cur[NN];
__device__ int2   g_edge[NE];                   // dst-sorted (src, val_bits)
// W transposed to [N][K=128], bf16 hi/lo split
__device__ __nv_bfloat16 g_w1hi[128 * 128];
__device__ __nv_bfloat16 g_w1lo[128 * 128];
__device__ __nv_bfloat16 g_w2hi[64 * 128];
__device__ __nv_bfloat16 g_w2lo[64 * 128];

// ---------------------------------------------------------------------------
// warp-MMA helpers (baseline PTX, works on plain compute_103 target)
// ---------------------------------------------------------------------------
__device__ __forceinline__ uint32_t smem_u32(const void* p) {
    uint32_t a;
    asm("{ .reg .u64 t; cvta.to.shared.u64 t, %1; cvt.u32.u64 %0, t; }" : "=r"(a) : "l"(p));
    return a;
}
__device__ __forceinline__ void ldsm4(uint32_t addr, uint32_t& r0, uint32_t& r1,
                                      uint32_t& r2, uint32_t& r3) {
    asm volatile("ldmatrix.sync.aligned.m8n8.x4.shared.b16 {%0,%1,%2,%3}, [%4];"
                 : "=r"(r0), "=r"(r1), "=r"(r2), "=r"(r3) : "r"(addr));
}
__device__ __forceinline__ void mma16816(float* d, const uint32_t* a, const uint32_t* b) {
    asm volatile("mma.sync.aligned.m16n8k16.row.col.f32.bf16.bf16.f32 "
                 "{%0,%1,%2,%3}, {%4,%5,%6,%7}, {%8,%9}, {%0,%1,%2,%3};"
                 : "+f"(d[0]), "+f"(d[1]), "+f"(d[2]), "+f"(d[3])
                 : "r"(a[0]), "r"(a[1]), "r"(a[2]), "r"(a[3]), "r"(b[0]), "r"(b[1]));
}
__device__ __forceinline__ uint32_t pack_bf16x2(__nv_bfloat16 a, __nv_bfloat16 b) {
    return (uint32_t)__bfloat16_as_ushort(a) | ((uint32_t)__bfloat16_as_ushort(b) << 16);
}

// ---------------------------------------------------------------------------
// prep_w: W[k][n] row-major -> Wt[n][k] bf16 hi/lo
// ---------------------------------------------------------------------------
__global__ void __launch_bounds__(256) prep_w(const float* __restrict__ W, int N,
                                              __nv_bfloat16* __restrict__ hi,
                                              __nv_bfloat16* __restrict__ lo) {
    const int total = 128 * N;
    for (int idx = blockIdx.x * blockDim.x + threadIdx.x; idx < total;
         idx += gridDim.x * blockDim.x) {
        const int k = idx / N, n = idx % N;
        const float v = W[idx];
        const __nv_bfloat16 h = __float2bfloat16(v);
        const __nv_bfloat16 l = __float2bfloat16(v - __bfloat162float(h));
        hi[n * 128 + k] = h;
        lo[n * 128 + k] = l;
    }
}

// ---------------------------------------------------------------------------
// HMMA GEMM: out16[128 rows, N] = X[rows,128] @ Wt  (bf16-split, 3 passes)
// ---------------------------------------------------------------------------
template <int N_DIM, bool RELU_BIAS>
__global__ void __launch_bounds__(256) gemm_mma(const float* __restrict__ X,
                                                const float* __restrict__ BIAS,
                                                const __nv_bfloat16* __restrict__ WHI,
                                                const __nv_bfloat16* __restrict__ WLO,
                                                __half* __restrict__ out) {
    extern __shared__ __nv_bfloat16 sm[];
    constexpr int LDS = 136;                 // padded row stride (elements)
    constexpr int AHI = 0;
    constexpr int ALO = 128 * LDS;
    constexpr int BHI = 2 * 128 * LDS;
    constexpr int BLO = BHI + N_DIM * LDS;
    constexpr int WN = N_DIM / 2;            // warp n-extent
    constexpr int NT = WN / 8;               // n-tiles per warp

    const int tid = threadIdx.x;
    const int wid = tid >> 5, lane = tid & 31;
    const int row0 = blockIdx.x * 128;
    const uint32_t smb = smem_u32(sm);

    // copy Wt hi/lo into padded smem rows (16B chunks)
    {
        const uint4* sh = (const uint4*)WHI;
        const uint4* sl = (const uint4*)WLO;
        for (int i = tid; i < N_DIM * 16; i += 256) {
            const int r = i >> 4, c = i & 15;
            *(uint4*)(sm + BHI + r * LDS + c * 8) = sh[i];
            *(uint4*)(sm + BLO + r * LDS + c * 8) = sl[i];
        }
    }

    // load + (optional bias/relu) + hi/lo split-convert the A tile
    {
        const int r = tid >> 1;
        const int kh = (tid & 1) * 64;
        const bool ok = (row0 + r) < NN;
        uint32_t* ahi = (uint32_t*)(sm + AHI + r * LDS + kh);
        uint32_t* alo = (uint32_t*)(sm + ALO + r * LDS + kh);
#pragma unroll
        for (int i = 0; i < 16; i++) {
            float4 v = make_float4(0.f, 0.f, 0.f, 0.f);
            if (ok) {
                v = *(const float4*)(X + (size_t)(row0 + r) * 128 + kh + i * 4);
                if (RELU_BIAS) {
                    const float4 bv = *(const float4*)(BIAS + kh + i * 4);
                    v.x = fmaxf(v.x + bv.x, 0.f);
                    v.y = fmaxf(v.y + bv.y, 0.f);
                    v.z = fmaxf(v.z + bv.z, 0.f);
                    v.w = fmaxf(v.w + bv.w, 0.f);
                }
            }
            const __nv_bfloat16 h0 = __float2bfloat16(v.x), h1 = __float2bfloat16(v.y);
            const __nv_bfloat16 h2 = __float2bfloat16(v.z), h3 = __float2bfloat16(v.w);
            const __nv_bfloat16 l0 = __float2bfloat16(v.x - __bfloat162float(h0));
            const __nv_bfloat16 l1 = __float2bfloat16(v.y - __bfloat162float(h1));
            const __nv_bfloat16 l2 = __float2bfloat16(v.z - __bfloat162float(h2));
            const __nv_bfloat16 l3 = __float2bfloat16(v.w - __bfloat162float(h3));
            ahi[i * 2] = pack_bf16x2(h0, h1);
            ahi[i * 2 + 1] = pack_bf16x2(h2, h3);
            alo[i * 2] = pack_bf16x2(l0, l1);
            alo[i * 2 + 1] = pack_bf16x2(l2, l3);
        }
    }
    __syncthreads();

    const int m0 = (wid & 3) * 32;
    const int n0 = (wid >> 2) * WN;

    float acc[2][NT][4];
#pragma unroll
    for (int mt = 0; mt < 2; mt++)
#pragma unroll
        for (int nt = 0; nt < NT; nt++)
#pragma unroll
            for (int j = 0; j < 4; j++) acc[mt][nt][j] = 0.f;

#pragma unroll
    for (int p = 0; p < 3; p++) {
        const int aoff = (p == 2) ? ALO : AHI;
        const int boff = (p == 1) ? BLO : BHI;
        const uint32_t abase = smb + 2 * aoff;
        const uint32_t bbase = smb + 2 * boff;
#pragma unroll
        for (int ks = 0; ks < 8; ks++) {
            uint32_t af[2][4];
#pragma unroll
            for (int mt = 0; mt < 2; mt++) {
                const int r = m0 + mt * 16 + (lane & 7) + ((lane >> 3) & 1) * 8;
                const int kk = ks * 16 + (lane >> 4) * 8;
                ldsm4(abase + (uint32_t)(r * LDS + kk) * 2,
                      af[mt][0], af[mt][1], af[mt][2], af[mt][3]);
            }
            uint32_t bf[NT][2];
#pragma unroll
            for (int np = 0; np < NT / 2; np++) {
                const int r = n0 + np * 16 + (lane >> 4) * 8 + (lane & 7);
                const int kk = ks * 16 + ((lane >> 3) & 1) * 8;
                uint32_t t0, t1, t2, t3;
                ldsm4(bbase + (uint32_t)(r * LDS + kk) * 2, t0, t1, t2, t3);
                bf[2 * np][0] = t0; bf[2 * np][1] = t1;
                bf[2 * np + 1][0] = t2; bf[2 * np + 1][1] = t3;
            }
#pragma unroll
            for (int mt = 0; mt < 2; mt++)
#pragma unroll
                for (int nt = 0; nt < NT; nt++) mma16816(acc[mt][nt], af[mt], bf[nt]);
        }
    }

    // epilogue: D frag -> global fp16
#pragma unroll
    for (int mt = 0; mt < 2; mt++) {
        const int r = row0 + m0 + mt * 16 + (lane >> 2);
#pragma unroll
        for (int nt = 0; nt < NT; nt++) {
            const int c = n0 + nt * 8 + (lane & 3) * 2;
            if (r < NN)
                *(__half2*)(out + (size_t)r * N_DIM + c) =
                    __floats2half2_rn(acc[mt][nt][0], acc[mt][nt][1]);
            if (r + 8 < NN)
                *(__half2*)(out + (size_t)(r + 8) * N_DIM + c) =
                    __floats2half2_rn(acc[mt][nt][2], acc[mt][nt][3]);
        }
    }
}

// ---------------------------------------------------------------------------
// CSR build: zero -> histogram -> scan -> scatter
// ---------------------------------------------------------------------------
__global__ void __launch_bounds__(256) zero_deg() {
    const int i = blockIdx.x * blockDim.x + threadIdx.x;
    if (i < NN) g_deg[i] = 0;
}
__global__ void __launch_bounds__(256) hist_kernel(const int* __restrict__ dst, int E) {
    const int i = blockIdx.x * blockDim.x + threadIdx.x;
    if (i < E) atomicAdd(&g_deg[dst[i]], 1);
}
__global__ void __launch_bounds__(1024) scan_kernel(int E) {
    __shared__ int ssum[1024];
    const int t = threadIdx.x;
    const int CH = (NN + 1023) / 1024;
    const int lo = t * CH, hi = min(lo + CH, NN);
    int s = 0;
    for (int i = lo; i < hi; i++) s += g_deg[i];
    const int mysum = s;
    ssum[t] = s;
    __syncthreads();
    for (int d = 1; d < 1024; d <<= 1) {
        int add = (t >= d) ? ssum[t - d] : 0;
        __syncthreads();
        ssum[t] += add;
        __syncthreads();
    }
    int run = ssum[t] - mysum;
    for (int i = lo; i < hi; i++) {
        g_off[i] = run;
        g_cur[i] = run;
        run += g_deg[i];
    }
    if (t == 1023) g_off[NN] = run;
}
__global__ void __launch_bounds__(256) scatter_kernel(const int* __restrict__ src,
                                                      const int* __restrict__ dst,
                                                      const float* __restrict__ vals, int E) {
    const int i = blockIdx.x * blockDim.x + threadIdx.x;
    if (i < E) {
        const int d = dst[i];
        const int p = atomicAdd(&g_cur[d], 1);
        g_edge[p] = make_int2(src[i], __float_as_int(vals[i]));
    }
}

// ---------------------------------------------------------------------------
// gather SpMM, wide lanes: 16B (8 halves) per lane, fp32 accumulate.
// D=128: 16 lanes/edge, 2 edges in flight; D=64: 8 lanes/edge, 4 edges.
// ---------------------------------------------------------------------------
__global__ void __launch_bounds__(256) spmm_gather128(const __half* __restrict__ X,
                                                      float* __restrict__ Y) {
    const int lane = threadIdx.x & 31;
    const int row = (blockIdx.x * blockDim.x + threadIdx.x) >> 5;
    if (row >= NN) return;
    const int beg = g_off[row], end = g_off[row + 1];
    const int sub = lane >> 4;       // which edge of the pair
    const int col = lane & 15;       // uint4 index within 256B row
    const uint4* Xv = (const uint4*)X;

    float acc[8];
#pragma unroll
    for (int i = 0; i < 8; i++) acc[i] = 0.f;

#pragma unroll 2
    for (int e = beg + sub; e < end; e += 2) {
        const int2 ee = g_edge[e];                       // broadcast within sub-group
        const float v = __int_as_float(ee.y);
        const uint4 xv = Xv[(size_t)ee.x * 16 + col];
        const __half2* hp = (const __half2*)&xv;
#pragma unroll
        for (int i = 0; i < 4; i++) {
            const float2 f = __half22float2(hp[i]);
            acc[2 * i] += v * f.x;
            acc[2 * i + 1] += v * f.y;
        }
    }
#pragma unroll
    for (int i = 0; i < 8; i++)
        acc[i] += __shfl_xor_sync(0xffffffffu, acc[i], 16);
    if (lane < 16) {
        *(float4*)(Y + (size_t)row * 128 + col * 8) =
            make_float4(acc[0], acc[1], acc[2], acc[3]);
        *(float4*)(Y + (size_t)row * 128 + col * 8 + 4) =
            make_float4(acc[4], acc[5], acc[6], acc[7]);
    }
}

__global__ void __launch_bounds__(256) spmm_gather64(const __half* __restrict__ X,
                                                     const float* __restrict__ B2,
                                                     float* __restrict__ Y) {
    const int lane = threadIdx.x & 31;
    const int row = (blockIdx.x * blockDim.x + threadIdx.x) >> 5;
    if (row >= NN) return;
    const int beg = g_off[row], end = g_off[row + 1];
    const int sub = lane >> 3;       // which edge of the quad
    const int col = lane & 7;        // uint4 index within 128B row
    const uint4* Xv = (const uint4*)X;

    float acc[8];
#pragma unroll
    for (int i = 0; i < 8; i++) acc[i] = 0.f;

#pragma unroll 2
    for (int e = beg + sub; e < end; e += 4) {
        const int2 ee = g_edge[e];
        const float v = __int_as_float(ee.y);
        const uint4 xv = Xv[(size_t)ee.x * 8 + col];
        const __half2* hp = (const __half2*)&xv;
#pragma unroll
        for (int i = 0; i < 4; i++) {
            const float2 f = __half22float2(hp[i]);
            acc[2 * i] += v * f.x;
            acc[2 * i + 1] += v * f.y;
        }
    }
#pragma unroll
    for (int i = 0; i < 8; i++) {
        acc[i] += __shfl_xor_sync(0xffffffffu, acc[i], 8);
        acc[i] += __shfl_xor_sync(0xffffffffu, acc[i], 16);
    }
    if (lane < 8) {
        const float4 b0 = *(const float4*)(B2 + col * 8);
        const float4 b1 = *(const float4*)(B2 + col * 8 + 4);
        *(float4*)(Y + (size_t)row * 64 + col * 8) =
            make_float4(acc[0] + b0.x, acc[1] + b0.y, acc[2] + b0.z, acc[3] + b0.w);
        *(float4*)(Y + (size_t)row * 64 + col * 8 + 4) =
            make_float4(acc[4] + b1.x, acc[5] + b1.y, acc[6] + b1.z, acc[7] + b1.w);
    }
}

// ---------------------------------------------------------------------------
extern "C" void kernel_launch(void* const* d_in, const int* in_sizes, int n_in,
                              void* d_out, int out_size) {
    const float* x  = (const float*)d_in[0];
    const int*   es = (const int*)d_in[1];
    const int*   ed = (const int*)d_in[2];
    const float* ev = (const float*)d_in[3];
    const float* W1 = (const float*)d_in[4];
    const float* b1 = (const float*)d_in[5];
    const float* W2 = (const float*)d_in[6];
    const float* b2 = (const float*)d_in[7];
    float* out = (float*)d_out;
    const int E = in_sizes[1];

    __half *t1, *t2;
    float* agg1;
    __nv_bfloat16 *w1hi, *w1lo, *w2hi, *w2lo;
    cudaGetSymbolAddress((void**)&t1, g_t1);
    cudaGetSymbolAddress((void**)&agg1, g_agg1);
    cudaGetSymbolAddress((void**)&t2, g_t2);
    cudaGetSymbolAddress((void**)&w1hi, g_w1hi);
    cudaGetSymbolAddress((void**)&w1lo, g_w1lo);
    cudaGetSymbolAddress((void**)&w2hi, g_w2hi);
    cudaGetSymbolAddress((void**)&w2lo, g_w2lo);

    constexpr int SM1 = (2 * 128 + 2 * 128) * 136 * 2;  // 139,264 B
    constexpr int SM2 = (2 * 128 + 2 * 64) * 136 * 2;   // 104,448 B
    cudaFuncSetAttribute(gemm_mma<128, false>, cudaFuncAttributeMaxDynamicSharedMemorySize, SM1);
    cudaFuncSetAttribute(gemm_mma<64, true>, cudaFuncAttributeMaxDynamicSharedMemorySize, SM2);

    const int eb = (E + 255) / 256;
    const int gemm_blocks = (NN + 127) / 128;       // 782
    const int spmm_blocks = (NN * 32 + 255) / 256;  // warp per row

    // Fork: CSR build on side stream, prep_w1+gemm_l1 on main stream.
    // (Stream/event created per call; few calls total, host-side only.)
    cudaStream_t s1;
    cudaEvent_t evFork, evJoin;
    cudaStreamCreateWithFlags(&s1, cudaStreamNonBlocking);
    cudaEventCreateWithFlags(&evFork, cudaEventDisableTiming);
    cudaEventCreateWithFlags(&evJoin, cudaEventDisableTiming);

    cudaEventRecord(evFork, 0);
    cudaStreamWaitEvent(s1, evFork, 0);

    // side stream: CSR build + W2 prep (only needed by gemm_l2)
    zero_deg<<<(NN + 255) / 256, 256, 0, s1>>>();
    hist_kernel<<<eb, 256, 0, s1>>>(ed, E);
    scan_kernel<<<1, 1024, 0, s1>>>(E);
    scatter_kernel<<<eb, 256, 0, s1>>>(es, ed, ev, E);
    prep_w<<<32, 256, 0, s1>>>(W2, 64, w2hi, w2lo);

    // main stream: t1 = x @ W1
    prep_w<<<64, 256>>>(W1, 128, w1hi, w1lo);
    gemm_mma<128, false><<<gemm_blocks, 256, SM1>>>(x, nullptr, w1hi, w1lo, t1);

    cudaEventRecord(evJoin, s1);
    cudaStreamWaitEvent(0, evJoin, 0);

    // agg1 = A @ t1
    spmm_gather128<<<spmm_blocks, 256>>>(t1, agg1);
    // t2 = relu(agg1 + b1) @ W2
    gemm_mma<64, true><<<gemm_blocks, 256, SM2>>>(agg1, b1, w2hi, w2lo, t2);
    // out = A @ t2 + b2
    spmm_gather64<<<spmm_blocks, 256>>>(t2, b2, out);
}

// round 7
// speedup vs baseline: 1.4737x; 1.1866x over previous
#include <cuda_runtime.h>
#include <cuda_bf16.h>
#include <cuda_fp16.h>
#include <cstdint>
#include <cstddef>

#define NN 100000
#define NE 1600000
#define IN_DIM 128
#define HID_DIM 128
#define LAT_DIM 64

// ---------------------------------------------------------------------------
// Scratch (no cudaMalloc allowed)
// ---------------------------------------------------------------------------
__device__ __half g_t1[(size_t)NN * HID_DIM];   // x @ W1           (fp16)
__device__ float  g_agg1[(size_t)NN * HID_DIM]; // A @ t1           (fp32)
__device__ __half g_t2[(size_t)NN * LAT_DIM];   // relu(agg1+b1)@W2 (fp16)
__device__ int    g_deg[NN];
__device__ int    g_off[NN + 1];
__device__ int    g_cur[NN];
__device__ int2   g_edge[NE];                   // dst-sorted (src, val_bits)
// W transposed to [N][K=128], bf16 hi/lo split
__device__ __nv_bfloat16 g_w1hi[128 * 128];
__device__ __nv_bfloat16 g_w1lo[128 * 128];
__device__ __nv_bfloat16 g_w2hi[64 * 128];
__device__ __nv_bfloat16 g_w2lo[64 * 128];

// ---------------------------------------------------------------------------
// warp-MMA helpers (baseline PTX, works on plain compute_103 target)
// ---------------------------------------------------------------------------
__device__ __forceinline__ uint32_t smem_u32(const void* p) {
    uint32_t a;
    asm("{ .reg .u64 t; cvta.to.shared.u64 t, %1; cvt.u32.u64 %0, t; }" : "=r"(a) : "l"(p));
    return a;
}
__device__ __forceinline__ void ldsm4(uint32_t addr, uint32_t& r0, uint32_t& r1,
                                      uint32_t& r2, uint32_t& r3) {
    asm volatile("ldmatrix.sync.aligned.m8n8.x4.shared.b16 {%0,%1,%2,%3}, [%4];"
                 : "=r"(r0), "=r"(r1), "=r"(r2), "=r"(r3) : "r"(addr));
}
__device__ __forceinline__ void mma16816(float* d, const uint32_t* a, const uint32_t* b) {
    asm volatile("mma.sync.aligned.m16n8k16.row.col.f32.bf16.bf16.f32 "
                 "{%0,%1,%2,%3}, {%4,%5,%6,%7}, {%8,%9}, {%0,%1,%2,%3};"
                 : "+f"(d[0]), "+f"(d[1]), "+f"(d[2]), "+f"(d[3])
                 : "r"(a[0]), "r"(a[1]), "r"(a[2]), "r"(a[3]), "r"(b[0]), "r"(b[1]));
}
__device__ __forceinline__ uint32_t pack_bf16x2(__nv_bfloat16 a, __nv_bfloat16 b) {
    return (uint32_t)__bfloat16_as_ushort(a) | ((uint32_t)__bfloat16_as_ushort(b) << 16);
}

// ---------------------------------------------------------------------------
// prep_w: W[k][n] row-major -> Wt[n][k] bf16 hi/lo
// ---------------------------------------------------------------------------
__global__ void __launch_bounds__(256) prep_w(const float* __restrict__ W, int N,
                                              __nv_bfloat16* __restrict__ hi,
                                              __nv_bfloat16* __restrict__ lo) {
    const int total = 128 * N;
    for (int idx = blockIdx.x * blockDim.x + threadIdx.x; idx < total;
         idx += gridDim.x * blockDim.x) {
        const int k = idx / N, n = idx % N;
        const float v = W[idx];
        const __nv_bfloat16 h = __float2bfloat16(v);
        const __nv_bfloat16 l = __float2bfloat16(v - __bfloat162float(h));
        hi[n * 128 + k] = h;
        lo[n * 128 + k] = l;
    }
}

// ---------------------------------------------------------------------------
// HMMA GEMM: out16[128 rows, N] = X[rows,128] @ Wt  (bf16-split, 3 passes)
// ---------------------------------------------------------------------------
template <int N_DIM, bool RELU_BIAS>
__global__ void __launch_bounds__(256) gemm_mma(const float* __restrict__ X,
                                                const float* __restrict__ BIAS,
                                                const __nv_bfloat16* __restrict__ WHI,
                                                const __nv_bfloat16* __restrict__ WLO,
                                                __half* __restrict__ out) {
    extern __shared__ __nv_bfloat16 sm[];
    constexpr int LDS = 136;                 // padded row stride (elements)
    constexpr int AHI = 0;
    constexpr int ALO = 128 * LDS;
    constexpr int BHI = 2 * 128 * LDS;
    constexpr int BLO = BHI + N_DIM * LDS;
    constexpr int WN = N_DIM / 2;            // warp n-extent
    constexpr int NT = WN / 8;               // n-tiles per warp

    const int tid = threadIdx.x;
    const int wid = tid >> 5, lane = tid & 31;
    const int row0 = blockIdx.x * 128;
    const uint32_t smb = smem_u32(sm);

    // copy Wt hi/lo into padded smem rows (16B chunks)
    {
        const uint4* sh = (const uint4*)WHI;
        const uint4* sl = (const uint4*)WLO;
        for (int i = tid; i < N_DIM * 16; i += 256) {
            const int r = i >> 4, c = i & 15;
            *(uint4*)(sm + BHI + r * LDS + c * 8) = sh[i];
            *(uint4*)(sm + BLO + r * LDS + c * 8) = sl[i];
        }
    }

    // load + (optional bias/relu) + hi/lo split-convert the A tile
    {
        const int r = tid >> 1;
        const int kh = (tid & 1) * 64;
        const bool ok = (row0 + r) < NN;
        uint32_t* ahi = (uint32_t*)(sm + AHI + r * LDS + kh);
        uint32_t* alo = (uint32_t*)(sm + ALO + r * LDS + kh);
#pragma unroll
        for (int i = 0; i < 16; i++) {
            float4 v = make_float4(0.f, 0.f, 0.f, 0.f);
            if (ok) {
                v = *(const float4*)(X + (size_t)(row0 + r) * 128 + kh + i * 4);
                if (RELU_BIAS) {
                    const float4 bv = *(const float4*)(BIAS + kh + i * 4);
                    v.x = fmaxf(v.x + bv.x, 0.f);
                    v.y = fmaxf(v.y + bv.y, 0.f);
                    v.z = fmaxf(v.z + bv.z, 0.f);
                    v.w = fmaxf(v.w + bv.w, 0.f);
                }
            }
            const __nv_bfloat16 h0 = __float2bfloat16(v.x), h1 = __float2bfloat16(v.y);
            const __nv_bfloat16 h2 = __float2bfloat16(v.z), h3 = __float2bfloat16(v.w);
            const __nv_bfloat16 l0 = __float2bfloat16(v.x - __bfloat162float(h0));
            const __nv_bfloat16 l1 = __float2bfloat16(v.y - __bfloat162float(h1));
            const __nv_bfloat16 l2 = __float2bfloat16(v.z - __bfloat162float(h2));
            const __nv_bfloat16 l3 = __float2bfloat16(v.w - __bfloat162float(h3));
            ahi[i * 2] = pack_bf16x2(h0, h1);
            ahi[i * 2 + 1] = pack_bf16x2(h2, h3);
            alo[i * 2] = pack_bf16x2(l0, l1);
            alo[i * 2 + 1] = pack_bf16x2(l2, l3);
        }
    }
    __syncthreads();

    const int m0 = (wid & 3) * 32;
    const int n0 = (wid >> 2) * WN;

    float acc[2][NT][4];
#pragma unroll
    for (int mt = 0; mt < 2; mt++)
#pragma unroll
        for (int nt = 0; nt < NT; nt++)
#pragma unroll
            for (int j = 0; j < 4; j++) acc[mt][nt][j] = 0.f;

#pragma unroll
    for (int p = 0; p < 3; p++) {
        const int aoff = (p == 2) ? ALO : AHI;
        const int boff = (p == 1) ? BLO : BHI;
        const uint32_t abase = smb + 2 * aoff;
        const uint32_t bbase = smb + 2 * boff;
#pragma unroll
        for (int ks = 0; ks < 8; ks++) {
            uint32_t af[2][4];
#pragma unroll
            for (int mt = 0; mt < 2; mt++) {
                const int r = m0 + mt * 16 + (lane & 7) + ((lane >> 3) & 1) * 8;
                const int kk = ks * 16 + (lane >> 4) * 8;
                ldsm4(abase + (uint32_t)(r * LDS + kk) * 2,
                      af[mt][0], af[mt][1], af[mt][2], af[mt][3]);
            }
            uint32_t bf[NT][2];
#pragma unroll
            for (int np = 0; np < NT / 2; np++) {
                const int r = n0 + np * 16 + (lane >> 4) * 8 + (lane & 7);
                const int kk = ks * 16 + ((lane >> 3) & 1) * 8;
                uint32_t t0, t1, t2, t3;
                ldsm4(bbase + (uint32_t)(r * LDS + kk) * 2, t0, t1, t2, t3);
                bf[2 * np][0] = t0; bf[2 * np][1] = t1;
                bf[2 * np + 1][0] = t2; bf[2 * np + 1][1] = t3;
            }
#pragma unroll
            for (int mt = 0; mt < 2; mt++)
#pragma unroll
                for (int nt = 0; nt < NT; nt++) mma16816(acc[mt][nt], af[mt], bf[nt]);
        }
    }

    // epilogue: D frag -> global fp16
#pragma unroll
    for (int mt = 0; mt < 2; mt++) {
        const int r = row0 + m0 + mt * 16 + (lane >> 2);
#pragma unroll
        for (int nt = 0; nt < NT; nt++) {
            const int c = n0 + nt * 8 + (lane & 3) * 2;
            if (r < NN)
                *(__half2*)(out + (size_t)r * N_DIM + c) =
                    __floats2half2_rn(acc[mt][nt][0], acc[mt][nt][1]);
            if (r + 8 < NN)
                *(__half2*)(out + (size_t)(r + 8) * N_DIM + c) =
                    __floats2half2_rn(acc[mt][nt][2], acc[mt][nt][3]);
        }
    }
}

// ---------------------------------------------------------------------------
// CSR build: histogram -> scan -> scatter (deg zeroed via memset node)
// ---------------------------------------------------------------------------
__global__ void __launch_bounds__(256) hist_kernel(const int* __restrict__ dst, int E) {
    const int i = blockIdx.x * blockDim.x + threadIdx.x;
    if (i < E) atomicAdd(&g_deg[dst[i]], 1);
}
__global__ void __launch_bounds__(1024) scan_kernel(int E) {
    __shared__ int ssum[1024];
    const int t = threadIdx.x;
    const int CH = (NN + 1023) / 1024;
    const int lo = t * CH, hi = min(lo + CH, NN);
    int s = 0;
    for (int i = lo; i < hi; i++) s += g_deg[i];
    const int mysum = s;
    ssum[t] = s;
    __syncthreads();
    for (int d = 1; d < 1024; d <<= 1) {
        int add = (t >= d) ? ssum[t - d] : 0;
        __syncthreads();
        ssum[t] += add;
        __syncthreads();
    }
    int run = ssum[t] - mysum;
    for (int i = lo; i < hi; i++) {
        g_off[i] = run;
        g_cur[i] = run;
        run += g_deg[i];
    }
    if (t == 1023) g_off[NN] = run;
}
__global__ void __launch_bounds__(256) scatter_kernel(const int* __restrict__ src,
                                                      const int* __restrict__ dst,
                                                      const float* __restrict__ vals, int E) {
    const int i = blockIdx.x * blockDim.x + threadIdx.x;
    if (i < E) {
        const int d = dst[i];
        const int p = atomicAdd(&g_cur[d], 1);
        g_edge[p] = make_int2(src[i], __float_as_int(vals[i]));
    }
}

// ---------------------------------------------------------------------------
// gather SpMM: one row per SUB-WARP (no cross-lane reduce), 16B lanes,
// 4-edge pipelined batches (4 record loads + 4 gathers in flight per lane).
// ---------------------------------------------------------------------------
__global__ void __launch_bounds__(256) spmm_gather128(const __half* __restrict__ X,
                                                      float* __restrict__ Y) {
    const int row = (blockIdx.x * blockDim.x + threadIdx.x) >> 4;  // 16 lanes/row
    if (row >= NN) return;
    const int col = threadIdx.x & 15;  // uint4 index in 256B fp16 row
    const int beg = g_off[row], end = g_off[row + 1];
    const uint4* Xv = (const uint4*)X;

    float acc[8];
#pragma unroll
    for (int i = 0; i < 8; i++) acc[i] = 0.f;

    int e = beg;
    for (; e + 4 <= end; e += 4) {
        const int2 r0 = g_edge[e], r1 = g_edge[e + 1];
        const int2 r2 = g_edge[e + 2], r3 = g_edge[e + 3];
        const uint4 x0 = Xv[(size_t)r0.x * 16 + col];
        const uint4 x1 = Xv[(size_t)r1.x * 16 + col];
        const uint4 x2 = Xv[(size_t)r2.x * 16 + col];
        const uint4 x3 = Xv[(size_t)r3.x * 16 + col];
        const float v0 = __int_as_float(r0.y), v1 = __int_as_float(r1.y);
        const float v2 = __int_as_float(r2.y), v3 = __int_as_float(r3.y);
        const __half2 *h0 = (const __half2*)&x0, *h1 = (const __half2*)&x1;
        const __half2 *h2 = (const __half2*)&x2, *h3 = (const __half2*)&x3;
#pragma unroll
        for (int i = 0; i < 4; i++) {
            float2 f;
            f = __half22float2(h0[i]); acc[2 * i] += v0 * f.x; acc[2 * i + 1] += v0 * f.y;
            f = __half22float2(h1[i]); acc[2 * i] += v1 * f.x; acc[2 * i + 1] += v1 * f.y;
            f = __half22float2(h2[i]); acc[2 * i] += v2 * f.x; acc[2 * i + 1] += v2 * f.y;
            f = __half22float2(h3[i]); acc[2 * i] += v3 * f.x; acc[2 * i + 1] += v3 * f.y;
        }
    }
    for (; e < end; e++) {
        const int2 ee = g_edge[e];
        const float v = __int_as_float(ee.y);
        const uint4 xv = Xv[(size_t)ee.x * 16 + col];
        const __half2* hp = (const __half2*)&xv;
#pragma unroll
        for (int i = 0; i < 4; i++) {
            const float2 f = __half22float2(hp[i]);
            acc[2 * i] += v * f.x;
            acc[2 * i + 1] += v * f.y;
        }
    }
    *(float4*)(Y + (size_t)row * 128 + col * 8) =
        make_float4(acc[0], acc[1], acc[2], acc[3]);
    *(float4*)(Y + (size_t)row * 128 + col * 8 + 4) =
        make_float4(acc[4], acc[5], acc[6], acc[7]);
}

__global__ void __launch_bounds__(256) spmm_gather64(const __half* __restrict__ X,
                                                     const float* __restrict__ B2,
                                                     float* __restrict__ Y) {
    const int row = (blockIdx.x * blockDim.x + threadIdx.x) >> 3;  // 8 lanes/row
    if (row >= NN) return;
    const int col = threadIdx.x & 7;   // uint4 index in 128B fp16 row
    const int beg = g_off[row], end = g_off[row + 1];
    const uint4* Xv = (const uint4*)X;

    float acc[8];
#pragma unroll
    for (int i = 0; i < 8; i++) acc[i] = 0.f;

    int e = beg;
    for (; e + 4 <= end; e += 4) {
        const int2 r0 = g_edge[e], r1 = g_edge[e + 1];
        const int2 r2 = g_edge[e + 2], r3 = g_edge[e + 3];
        const uint4 x0 = Xv[(size_t)r0.x * 8 + col];
        const uint4 x1 = Xv[(size_t)r1.x * 8 + col];
        const uint4 x2 = Xv[(size_t)r2.x * 8 + col];
        const uint4 x3 = Xv[(size_t)r3.x * 8 + col];
        const float v0 = __int_as_float(r0.y), v1 = __int_as_float(r1.y);
        const float v2 = __int_as_float(r2.y), v3 = __int_as_float(r3.y);
        const __half2 *h0 = (const __half2*)&x0, *h1 = (const __half2*)&x1;
        const __half2 *h2 = (const __half2*)&x2, *h3 = (const __half2*)&x3;
#pragma unroll
        for (int i = 0; i < 4; i++) {
            float2 f;
            f = __half22float2(h0[i]); acc[2 * i] += v0 * f.x; acc[2 * i + 1] += v0 * f.y;
            f = __half22float2(h1[i]); acc[2 * i] += v1 * f.x; acc[2 * i + 1] += v1 * f.y;
            f = __half22float2(h2[i]); acc[2 * i] += v2 * f.x; acc[2 * i + 1] += v2 * f.y;
            f = __half22float2(h3[i]); acc[2 * i] += v3 * f.x; acc[2 * i + 1] += v3 * f.y;
        }
    }
    for (; e < end; e++) {
        const int2 ee = g_edge[e];
        const float v = __int_as_float(ee.y);
        const uint4 xv = Xv[(size_t)ee.x * 8 + col];
        const __half2* hp = (const __half2*)&xv;
#pragma unroll
        for (int i = 0; i < 4; i++) {
            const float2 f = __half22float2(hp[i]);
            acc[2 * i] += v * f.x;
            acc[2 * i + 1] += v * f.y;
        }
    }
    const float4 b0 = *(const float4*)(B2 + col * 8);
    const float4 b1 = *(const float4*)(B2 + col * 8 + 4);
    *(float4*)(Y + (size_t)row * 64 + col * 8) =
        make_float4(acc[0] + b0.x, acc[1] + b0.y, acc[2] + b0.z, acc[3] + b0.w);
    *(float4*)(Y + (size_t)row * 64 + col * 8 + 4) =
        make_float4(acc[4] + b1.x, acc[5] + b1.y, acc[6] + b1.z, acc[7] + b1.w);
}

// ---------------------------------------------------------------------------
extern "C" void kernel_launch(void* const* d_in, const int* in_sizes, int n_in,
                              void* d_out, int out_size) {
    const float* x  = (const float*)d_in[0];
    const int*   es = (const int*)d_in[1];
    const int*   ed = (const int*)d_in[2];
    const float* ev = (const float*)d_in[3];
    const float* W1 = (const float*)d_in[4];
    const float* b1 = (const float*)d_in[5];
    const float* W2 = (const float*)d_in[6];
    const float* b2 = (const float*)d_in[7];
    float* out = (float*)d_out;
    const int E = in_sizes[1];

    __half *t1, *t2;
    float* agg1;
    int* degp;
    __nv_bfloat16 *w1hi, *w1lo, *w2hi, *w2lo;
    cudaGetSymbolAddress((void**)&t1, g_t1);
    cudaGetSymbolAddress((void**)&agg1, g_agg1);
    cudaGetSymbolAddress((void**)&t2, g_t2);
    cudaGetSymbolAddress((void**)&degp, g_deg);
    cudaGetSymbolAddress((void**)&w1hi, g_w1hi);
    cudaGetSymbolAddress((void**)&w1lo, g_w1lo);
    cudaGetSymbolAddress((void**)&w2hi, g_w2hi);
    cudaGetSymbolAddress((void**)&w2lo, g_w2lo);

    constexpr int SM1 = (2 * 128 + 2 * 128) * 136 * 2;  // 139,264 B
    constexpr int SM2 = (2 * 128 + 2 * 64) * 136 * 2;   // 104,448 B
    cudaFuncSetAttribute(gemm_mma<128, false>, cudaFuncAttributeMaxDynamicSharedMemorySize, SM1);
    cudaFuncSetAttribute(gemm_mma<64, true>, cudaFuncAttributeMaxDynamicSharedMemorySize, SM2);

    const int eb = (E + 255) / 256;
    const int gemm_blocks = (NN + 127) / 128;  // 782

    // Fork: CSR build on side stream, prep_w1+gemm_l1 on main stream.
    cudaStream_t s1;
    cudaEvent_t evFork, evJoin;
    cudaStreamCreateWithFlags(&s1, cudaStreamNonBlocking);
    cudaEventCreateWithFlags(&evFork, cudaEventDisableTiming);
    cudaEventCreateWithFlags(&evJoin, cudaEventDisableTiming);

    cudaEventRecord(evFork, 0);
    cudaStreamWaitEvent(s1, evFork, 0);

    // side stream: CSR build + W2 prep (only needed by gemm_l2)
    cudaMemsetAsync(degp, 0, NN * sizeof(int), s1);
    hist_kernel<<<eb, 256, 0, s1>>>(ed, E);
    scan_kernel<<<1, 1024, 0, s1>>>(E);
    scatter_kernel<<<eb, 256, 0, s1>>>(es, ed, ev, E);
    prep_w<<<32, 256, 0, s1>>>(W2, 64, w2hi, w2lo);

    // main stream: t1 = x @ W1
    prep_w<<<64, 256>>>(W1, 128, w1hi, w1lo);
    gemm_mma<128, false><<<gemm_blocks, 256, SM1>>>(x, nullptr, w1hi, w1lo, t1);

    cudaEventRecord(evJoin, s1);
    cudaStreamWaitEvent(0, evJoin, 0);

    // agg1 = A @ t1   (row per 16-lane sub-warp)
    spmm_gather128<<<(NN * 16 + 255) / 256, 256>>>(t1, agg1);
    // t2 = relu(agg1 + b1) @ W2
    gemm_mma<64, true><<<gemm_blocks, 256, SM2>>>(agg1, b1, w2hi, w2lo, t2);
    // out = A @ t2 + b2  (row per 8-lane sub-warp)
    spmm_gather64<<<(NN * 8 + 255) / 256, 256>>>(t2, b2, out);
}